// round 2
// baseline (speedup 1.0000x reference)
#include <cuda_runtime.h>
#include <cuda_bf16.h>
#include <math.h>

// Problem constants
#define BB   16
#define KK   32
#define HH   28
#define WW   28
#define HID  64
#define OUT  64
#define NIMG (BB*KK)          // 512

// ---------------- scratch (device globals; no allocation) ----------------
__device__ float g_h1[NIMG * 32 * 14 * 14];   // conv1+pool out
__device__ float g_h2[NIMG * 64 * 7 * 7];     // conv2+pool out
__device__ float g_feat[NIMG * HID];          // fc out
__device__ float g_part[NIMG * OUT];          // per-(b,i) partial relu-sums

// =========================================================================
// Kernel 1: conv1 (1->32, 3x3 SAME) + relu + maxpool2 : (512,1,28,28)->(512,32,14,14)
// =========================================================================
__global__ __launch_bounds__(256) void conv1_kernel(
    const float* __restrict__ x, const float* __restrict__ w,
    const float* __restrict__ bias)
{
    __shared__ float sin1[30 * 30];   // zero-padded input
    __shared__ float sw1[32 * 9];
    __shared__ float sb1[32];

    const int img = blockIdx.x;
    const int tid = threadIdx.x;

    for (int i = tid; i < 900; i += 256) sin1[i] = 0.f;
    for (int i = tid; i < 288; i += 256) sw1[i] = w[i];
    if (tid < 32) sb1[tid] = bias[tid];
    __syncthreads();
    for (int i = tid; i < 784; i += 256) {
        int y = i / 28, xx = i % 28;
        sin1[(y + 1) * 30 + xx + 1] = x[img * 784 + i];
    }
    __syncthreads();

    // outputs: 32ch * 14*14
    for (int item = tid; item < 32 * 196; item += 256) {
        int c = item / 196, p = item % 196;
        int oy = p / 14, ox = p % 14;
        const float* wp = sw1 + c * 9;
        const float bv = sb1[c];
        float m = 0.f;  // relu floor
        #pragma unroll
        for (int py = 0; py < 2; py++) {
            #pragma unroll
            for (int px = 0; px < 2; px++) {
                int r = 2 * oy + py, col = 2 * ox + px;
                float s = bv;
                #pragma unroll
                for (int ky = 0; ky < 3; ky++)
                    #pragma unroll
                    for (int kx = 0; kx < 3; kx++)
                        s += sin1[(r + ky) * 30 + col + kx] * wp[ky * 3 + kx];
                m = fmaxf(m, s);
            }
        }
        g_h1[img * (32 * 196) + item] = m;
    }
}

// =========================================================================
// Kernel 2: conv2 (32->64, 3x3 SAME) + relu + maxpool2 : ->(512,64,7,7)
// Thread tile: 16 output channels x 2x2 pool window = 64 fp32 accumulators.
// smem: padded input 32x16x16 (32KB) + weights [ic][ky][kx][c] (72KB).
// =========================================================================
#define CONV2_SMEM ((8192 + 18432 + 64) * 4)
__global__ __launch_bounds__(256) void conv2_kernel(
    const float* __restrict__ w, const float* __restrict__ bias)
{
    extern __shared__ float sm2[];
    float* sin2 = sm2;                 // 32 * 16*16
    float* sw2  = sm2 + 8192;          // [f=ic*9+r][c] : 288*64
    float* sb2  = sw2 + 18432;         // 64

    const int img = blockIdx.x;
    const int tid = threadIdx.x;

    for (int i = tid; i < 8192; i += 256) sin2[i] = 0.f;
    for (int idx = tid; idx < 18432; idx += 256) {
        int f = idx >> 6, c = idx & 63;
        int ic = f / 9, r = f % 9;
        sw2[idx] = w[(c * 32 + ic) * 9 + r];
    }
    if (tid < 64) sb2[tid] = bias[tid];
    __syncthreads();
    for (int i = tid; i < 32 * 196; i += 256) {
        int ic = i / 196, p = i % 196;
        int y = p / 14, xx = p % 14;
        sin2[ic * 256 + (y + 1) * 16 + xx + 1] = g_h1[img * (32 * 196) + i];
    }
    __syncthreads();

    if (tid < 196) {
        const int cg  = tid / 49;      // 4 groups of 16 channels
        const int pos = tid % 49;
        const int oy = pos / 7, ox = pos % 7;
        const int c0 = cg * 16;
        const int iy = 2 * oy, ix = 2 * ox;

        float acc[4][16];
        #pragma unroll
        for (int p = 0; p < 4; p++)
            #pragma unroll
            for (int q = 0; q < 16; q++) acc[p][q] = 0.f;

        for (int ic = 0; ic < 32; ic++) {
            const float* ip = sin2 + ic * 256;
            #pragma unroll
            for (int ky = 0; ky < 3; ky++) {
                const float* r0 = ip + (iy + ky) * 16 + ix;
                const float* r1 = r0 + 16;
                #pragma unroll
                for (int kx = 0; kx < 3; kx++) {
                    float i00 = r0[kx], i01 = r0[kx + 1];
                    float i10 = r1[kx], i11 = r1[kx + 1];
                    const float* wp = sw2 + ((ic * 3 + ky) * 3 + kx) * 64 + c0;
                    #pragma unroll
                    for (int q = 0; q < 4; q++) {
                        float4 wv = *(const float4*)(wp + q * 4);
                        acc[0][q*4+0] += i00 * wv.x; acc[0][q*4+1] += i00 * wv.y;
                        acc[0][q*4+2] += i00 * wv.z; acc[0][q*4+3] += i00 * wv.w;
                        acc[1][q*4+0] += i01 * wv.x; acc[1][q*4+1] += i01 * wv.y;
                        acc[1][q*4+2] += i01 * wv.z; acc[1][q*4+3] += i01 * wv.w;
                        acc[2][q*4+0] += i10 * wv.x; acc[2][q*4+1] += i10 * wv.y;
                        acc[2][q*4+2] += i10 * wv.z; acc[2][q*4+3] += i10 * wv.w;
                        acc[3][q*4+0] += i11 * wv.x; acc[3][q*4+1] += i11 * wv.y;
                        acc[3][q*4+2] += i11 * wv.z; acc[3][q*4+3] += i11 * wv.w;
                    }
                }
            }
        }
        #pragma unroll
        for (int ch = 0; ch < 16; ch++) {
            float bv = sb2[c0 + ch];
            float m = fmaxf(fmaxf(acc[0][ch], acc[1][ch]),
                            fmaxf(acc[2][ch], acc[3][ch])) + bv;
            m = fmaxf(m, 0.f);
            g_h2[img * 3136 + (c0 + ch) * 49 + pos] = m;
        }
    }
}

// =========================================================================
// Kernel 3: fc  feat = relu(h2flat[512,3136] @ fc_w.T + fc_b) -> (512,64)
// 64 blocks x 8 warps; warp owns one image, loops all 64 outputs.
// =========================================================================
__global__ __launch_bounds__(256) void fc_kernel(
    const float* __restrict__ fcw, const float* __restrict__ fcb)
{
    const int wid  = threadIdx.x >> 5;
    const int lane = threadIdx.x & 31;
    const int img  = blockIdx.x * 8 + wid;
    const float* arow = g_h2 + img * 3136;

    for (int o = 0; o < 64; o++) {
        const float* wrow = fcw + o * 3136;
        float s = 0.f;
        #pragma unroll 7
        for (int i = lane; i < 3136; i += 32)
            s += arow[i] * wrow[i];
        #pragma unroll
        for (int off = 16; off; off >>= 1)
            s += __shfl_xor_sync(0xffffffffu, s, off);
        if (lane == 0)
            g_feat[img * 64 + o] = fmaxf(s + fcb[o], 0.f);
    }
}

// =========================================================================
// Kernel 4: Eq3to3 + relu + mean(ijk), factorized through Abar.
// One block per (b,i). For all (j,k):
//   x6[e,j,k] = sum_d V[d,e] a_j a_k + gk[k,e] + gj[j,e] + ssb[e]
// with  V  = w0*a_i + w1*Abar
//       Ck = Abar*(w2*a_i + w4*Abar),  gk[k,e]=sum_d Ck[d,e] a_k[d]
//       Cj = Abar*(w3*a_i + w5*Abar),  gj[j,e]=sum_d Cj[d,e] a_j[d]
//       ssb= sum_d Abar^2*(w6*a_i + w7*Abar) + eq_b
// Epilogue: relu, per-thread sum over jk -> deterministic block reduce.
// =========================================================================
#define EQ_SMEM ((2080 + 64 + 3*4352 + 2*2048 + 64 + 2048) * 4)
__global__ __launch_bounds__(256) void eq_kernel(
    const float* __restrict__ eqw, const float* __restrict__ eqb)
{
    extern __shared__ float sm[];
    float* sa   = sm;            // [k][d] pad 65 : 2080
    float* sAb  = sa  + 2080;    // 64
    float* sV   = sAb + 64;      // [d][e] pad 68 : 4352
    float* sCk  = sV  + 4352;    // 4352
    float* sCj  = sCk + 4352;    // 4352
    float* sgk  = sCj + 4352;    // [k][e] : 2048
    float* sgj  = sgk + 2048;    // [j][e] : 2048
    float* ssb  = sgj + 2048;    // 64
    float* sred = ssb + 64;      // [jkg][e] : 2048

    const int b   = blockIdx.x >> 5;
    const int ii  = blockIdx.x & 31;
    const int tid = threadIdx.x;

    const float* fb = g_feat + b * KK * HID;
    for (int idx = tid; idx < 2048; idx += 256) {
        int k = idx >> 6, d = idx & 63;
        sa[k * 65 + d] = fb[idx];
    }
    __syncthreads();
    if (tid < 64) {
        float s = 0.f;
        #pragma unroll
        for (int k = 0; k < 32; k++) s += sa[k * 65 + tid];
        sAb[tid] = s * (1.0f / 32.0f);
    }
    __syncthreads();

    for (int idx = tid; idx < 4096; idx += 256) {
        int d = idx >> 6, e = idx & 63;
        const float4* wp = (const float4*)(eqw + (size_t)idx * 8);
        float4 wA = wp[0];   // w0 w1 w2 w3
        float4 wB = wp[1];   // w4 w5 w6 w7
        float ai = sa[ii * 65 + d], ab = sAb[d];
        sV [d * 68 + e] = wA.x * ai + wA.y * ab;
        sCk[d * 68 + e] = ab * (wA.z * ai + wB.x * ab);
        sCj[d * 68 + e] = ab * (wA.w * ai + wB.y * ab);
    }
    if (tid < 64) {
        int e = tid;
        float s = 0.f;
        for (int d = 0; d < 64; d++) {
            float ab = sAb[d];
            float2 w67 = *(const float2*)(eqw + ((size_t)(d * 64 + e)) * 8 + 6);
            s += ab * ab * (w67.x * sa[ii * 65 + d] + w67.y * ab);
        }
        ssb[e] = s + eqb[e];
    }
    __syncthreads();

    for (int idx = tid; idx < 2048; idx += 256) {
        int k = idx >> 6, e = idx & 63;
        float s1 = 0.f, s2 = 0.f;
        #pragma unroll 8
        for (int d = 0; d < 64; d++) {
            float ak = sa[k * 65 + d];
            s1 += sCk[d * 68 + e] * ak;
            s2 += sCj[d * 68 + e] * ak;
        }
        sgk[k * 64 + e] = s1;
        sgj[k * 64 + e] = s2;
    }
    __syncthreads();

    const int eg  = tid & 7;        // 8 e-groups of 8
    const int jkg = tid >> 3;       // 32 jk-groups of 8
    float sb_r[8];
    #pragma unroll
    for (int v = 0; v < 8; v++) sb_r[v] = ssb[eg * 8 + v];

    float esum[8];
    #pragma unroll
    for (int v = 0; v < 8; v++) esum[v] = 0.f;

    for (int pass = 0; pass < 4; pass++) {
        const int jkbase = pass * 256 + jkg * 8;
        const int j  = jkbase >> 5;
        const int k0 = jkbase & 31;

        float acc[8][8];
        #pragma unroll
        for (int u = 0; u < 8; u++)
            #pragma unroll
            for (int v = 0; v < 8; v++) acc[u][v] = 0.f;

        const float* ajp = sa + j * 65;
        for (int d = 0; d < 64; d++) {
            float aj = ajp[d];
            float pr[8];
            #pragma unroll
            for (int u = 0; u < 8; u++) pr[u] = aj * sa[(k0 + u) * 65 + d];
            float4 v0 = *(const float4*)(sV + d * 68 + eg * 8);
            float4 v1 = *(const float4*)(sV + d * 68 + eg * 8 + 4);
            #pragma unroll
            for (int u = 0; u < 8; u++) {
                acc[u][0] += pr[u] * v0.x; acc[u][1] += pr[u] * v0.y;
                acc[u][2] += pr[u] * v0.z; acc[u][3] += pr[u] * v0.w;
                acc[u][4] += pr[u] * v1.x; acc[u][5] += pr[u] * v1.y;
                acc[u][6] += pr[u] * v1.z; acc[u][7] += pr[u] * v1.w;
            }
        }

        float4 gj0 = *(const float4*)(sgj + j * 64 + eg * 8);
        float4 gj1 = *(const float4*)(sgj + j * 64 + eg * 8 + 4);
        float gjv[8] = {gj0.x, gj0.y, gj0.z, gj0.w, gj1.x, gj1.y, gj1.z, gj1.w};
        #pragma unroll
        for (int u = 0; u < 8; u++) {
            float4 gk0 = *(const float4*)(sgk + (k0 + u) * 64 + eg * 8);
            float4 gk1 = *(const float4*)(sgk + (k0 + u) * 64 + eg * 8 + 4);
            float gkv[8] = {gk0.x, gk0.y, gk0.z, gk0.w, gk1.x, gk1.y, gk1.z, gk1.w};
            #pragma unroll
            for (int v = 0; v < 8; v++) {
                float val = acc[u][v] + gjv[v] + gkv[v] + sb_r[v];
                esum[v] += fmaxf(val, 0.f);
            }
        }
    }

    #pragma unroll
    for (int v = 0; v < 8; v++) sred[jkg * 64 + eg * 8 + v] = esum[v];
    __syncthreads();
    if (tid < 64) {
        float s = 0.f;
        #pragma unroll
        for (int g = 0; g < 32; g++) s += sred[g * 64 + tid];
        g_part[blockIdx.x * 64 + tid] = s;
    }
}

// =========================================================================
// Kernel 5: final  out[b] = sum_e relu(mean_ijk) * out_w[e] + out_b
// =========================================================================
__global__ __launch_bounds__(64) void final_kernel(
    const float* __restrict__ outw, const float* __restrict__ outb,
    float* __restrict__ out)
{
    __shared__ float red[64];
    const int b = blockIdx.x, e = threadIdx.x;
    float s = 0.f;
    #pragma unroll
    for (int i = 0; i < 32; i++) s += g_part[(b * 32 + i) * 64 + e];
    float x8 = s * (1.0f / 32768.0f);
    red[e] = fmaxf(x8, 0.f) * outw[e];
    __syncthreads();
    #pragma unroll
    for (int off = 32; off; off >>= 1) {
        if (e < off) red[e] += red[e + off];
        __syncthreads();
    }
    if (e == 0) out[b] = red[0] + outb[0];
}

// =========================================================================
extern "C" void kernel_launch(void* const* d_in, const int* in_sizes, int n_in,
                              void* d_out, int out_size)
{
    const float* x    = (const float*)d_in[0];
    const float* c1w  = (const float*)d_in[1];
    const float* c1b  = (const float*)d_in[2];
    const float* c2w  = (const float*)d_in[3];
    const float* c2b  = (const float*)d_in[4];
    const float* fcw  = (const float*)d_in[5];
    const float* fcb  = (const float*)d_in[6];
    const float* eqw  = (const float*)d_in[7];
    const float* eqb  = (const float*)d_in[8];
    const float* outw = (const float*)d_in[9];
    const float* outb = (const float*)d_in[10];
    float* out = (float*)d_out;

    cudaFuncSetAttribute(conv2_kernel, cudaFuncAttributeMaxDynamicSharedMemorySize, CONV2_SMEM);
    cudaFuncSetAttribute(eq_kernel,    cudaFuncAttributeMaxDynamicSharedMemorySize, EQ_SMEM);

    conv1_kernel<<<NIMG, 256>>>(x, c1w, c1b);
    conv2_kernel<<<NIMG, 256, CONV2_SMEM>>>(c2w, c2b);
    fc_kernel<<<64, 256>>>(fcw, fcb);
    eq_kernel<<<NIMG, 256, EQ_SMEM>>>(eqw, eqb);
    final_kernel<<<BB, 64>>>(outw, outb, out);
}

// round 3
// speedup vs baseline: 1.6648x; 1.6648x over previous
#include <cuda_runtime.h>
#include <cuda_bf16.h>
#include <math.h>

#define BB   16
#define KK   32
#define HH   28
#define WW   28
#define HID  64
#define OUT  64
#define NIMG (BB*KK)          // 512

typedef unsigned long long u64;

// ---------------- scratch ----------------
__device__ float g_h1[NIMG * 32 * 14 * 14];
__device__ float g_h2[NIMG * 64 * 7 * 7];
__device__ float g_feat[NIMG * HID];
__device__ float g_part[NIMG * OUT];

// ---------------- packed fp32x2 helpers ----------------
__device__ __forceinline__ u64 pack2(float x, float y) {
    u64 r; asm("mov.b64 %0,{%1,%2};" : "=l"(r) : "f"(x), "f"(y)); return r;
}
__device__ __forceinline__ void unpack2(u64 p, float& x, float& y) {
    asm("mov.b64 {%0,%1},%2;" : "=f"(x), "=f"(y) : "l"(p));
}
__device__ __forceinline__ u64 ffma2(u64 a, u64 b, u64 c) {
    u64 d; asm("fma.rn.f32x2 %0,%1,%2,%3;" : "=l"(d) : "l"(a), "l"(b), "l"(c)); return d;
}

// =========================================================================
// Kernel 1: conv1 (1->32, 3x3 SAME) + relu + maxpool2
// =========================================================================
__global__ __launch_bounds__(256) void conv1_kernel(
    const float* __restrict__ x, const float* __restrict__ w,
    const float* __restrict__ bias)
{
    __shared__ float sin1[30 * 30];
    __shared__ float sw1[32 * 9];
    __shared__ float sb1[32];

    const int img = blockIdx.x;
    const int tid = threadIdx.x;

    for (int i = tid; i < 900; i += 256) sin1[i] = 0.f;
    for (int i = tid; i < 288; i += 256) sw1[i] = w[i];
    if (tid < 32) sb1[tid] = bias[tid];
    __syncthreads();
    for (int i = tid; i < 784; i += 256) {
        int y = i / 28, xx = i % 28;
        sin1[(y + 1) * 30 + xx + 1] = x[img * 784 + i];
    }
    __syncthreads();

    for (int item = tid; item < 32 * 196; item += 256) {
        int c = item / 196, p = item % 196;
        int oy = p / 14, ox = p % 14;
        const float* wp = sw1 + c * 9;
        const float bv = sb1[c];
        float m = 0.f;
        #pragma unroll
        for (int py = 0; py < 2; py++) {
            #pragma unroll
            for (int px = 0; px < 2; px++) {
                int r = 2 * oy + py, col = 2 * ox + px;
                float s = bv;
                #pragma unroll
                for (int ky = 0; ky < 3; ky++)
                    #pragma unroll
                    for (int kx = 0; kx < 3; kx++)
                        s += sin1[(r + ky) * 30 + col + kx] * wp[ky * 3 + kx];
                m = fmaxf(m, s);
            }
        }
        g_h1[img * (32 * 196) + item] = m;
    }
}

// =========================================================================
// Kernel 2: conv2 (32->64) + relu + maxpool2, fp32x2 packed FMA
// Thread: 16 out-channels (8 pairs) x 2x2 pool window.
// =========================================================================
#define CONV2_SMEM ((8192 + 18432 + 64) * 4)
__global__ __launch_bounds__(256) void conv2_kernel(
    const float* __restrict__ w, const float* __restrict__ bias)
{
    extern __shared__ float sm2[];
    float* sin2 = sm2;                 // 32 * 16*16
    float* sw2  = sm2 + 8192;          // [ic*9+r][c] : 288*64
    float* sb2  = sw2 + 18432;

    const int img = blockIdx.x;
    const int tid = threadIdx.x;

    for (int i = tid; i < 8192; i += 256) sin2[i] = 0.f;
    for (int idx = tid; idx < 18432; idx += 256) {
        int f = idx >> 6, c = idx & 63;
        int ic = f / 9, r = f % 9;
        sw2[idx] = w[(c * 32 + ic) * 9 + r];
    }
    if (tid < 64) sb2[tid] = bias[tid];
    __syncthreads();
    for (int i = tid; i < 32 * 196; i += 256) {
        int ic = i / 196, p = i % 196;
        int y = p / 14, xx = p % 14;
        sin2[ic * 256 + (y + 1) * 16 + xx + 1] = g_h1[img * (32 * 196) + i];
    }
    __syncthreads();

    if (tid < 196) {
        const int cg  = tid / 49;
        const int pos = tid % 49;
        const int oy = pos / 7, ox = pos % 7;
        const int c0 = cg * 16;
        const int iy = 2 * oy, ix = 2 * ox;

        u64 acc2[4][8];
        #pragma unroll
        for (int p = 0; p < 4; p++)
            #pragma unroll
            for (int q = 0; q < 8; q++) acc2[p][q] = 0ull;

        for (int ic = 0; ic < 32; ic++) {
            const float* ip = sin2 + ic * 256;
            #pragma unroll
            for (int ky = 0; ky < 3; ky++) {
                const float* r0 = ip + (iy + ky) * 16 + ix;
                const float* r1 = r0 + 16;
                #pragma unroll
                for (int kx = 0; kx < 3; kx++) {
                    u64 d00 = pack2(r0[kx],     r0[kx]);
                    u64 d01 = pack2(r0[kx + 1], r0[kx + 1]);
                    u64 d10 = pack2(r1[kx],     r1[kx]);
                    u64 d11 = pack2(r1[kx + 1], r1[kx + 1]);
                    const float* wp = sw2 + ((ic * 3 + ky) * 3 + kx) * 64 + c0;
                    ulonglong2 wA = *(const ulonglong2*)(wp);
                    ulonglong2 wB = *(const ulonglong2*)(wp + 4);
                    ulonglong2 wC = *(const ulonglong2*)(wp + 8);
                    ulonglong2 wD = *(const ulonglong2*)(wp + 12);
                    u64 wv[8] = {wA.x, wA.y, wB.x, wB.y, wC.x, wC.y, wD.x, wD.y};
                    #pragma unroll
                    for (int q = 0; q < 8; q++) {
                        acc2[0][q] = ffma2(d00, wv[q], acc2[0][q]);
                        acc2[1][q] = ffma2(d01, wv[q], acc2[1][q]);
                        acc2[2][q] = ffma2(d10, wv[q], acc2[2][q]);
                        acc2[3][q] = ffma2(d11, wv[q], acc2[3][q]);
                    }
                }
            }
        }
        #pragma unroll
        for (int q = 0; q < 8; q++) {
            float a0[4], a1[4];
            #pragma unroll
            for (int p = 0; p < 4; p++) unpack2(acc2[p][q], a0[p], a1[p]);
            float b0 = sb2[c0 + 2 * q], b1 = sb2[c0 + 2 * q + 1];
            float m0 = fmaxf(fmaxf(a0[0], a0[1]), fmaxf(a0[2], a0[3])) + b0;
            float m1 = fmaxf(fmaxf(a1[0], a1[1]), fmaxf(a1[2], a1[3])) + b1;
            g_h2[img * 3136 + (c0 + 2 * q) * 49 + pos]     = fmaxf(m0, 0.f);
            g_h2[img * 3136 + (c0 + 2 * q + 1) * 49 + pos] = fmaxf(m1, 0.f);
        }
    }
}

// =========================================================================
// Kernel 3: fc  feat = relu(h2flat[512,3136] @ fc_w.T + fc_b) -> (512,64)
// warp = image; 8 outputs per activation float4 load.
// =========================================================================
__global__ __launch_bounds__(256) void fc_kernel(
    const float* __restrict__ fcw, const float* __restrict__ fcb)
{
    const int wid  = threadIdx.x >> 5;
    const int lane = threadIdx.x & 31;
    const int img  = blockIdx.x * 8 + wid;
    const float4* arow = (const float4*)(g_h2 + img * 3136);

    for (int og = 0; og < 8; og++) {
        float s[8];
        #pragma unroll
        for (int o = 0; o < 8; o++) s[o] = 0.f;
        for (int i4 = lane; i4 < 784; i4 += 32) {
            float4 a = arow[i4];
            #pragma unroll
            for (int o = 0; o < 8; o++) {
                const float4* wr = (const float4*)(fcw + (size_t)(og * 8 + o) * 3136);
                float4 wv = wr[i4];
                s[o] += a.x * wv.x + a.y * wv.y + a.z * wv.z + a.w * wv.w;
            }
        }
        #pragma unroll
        for (int o = 0; o < 8; o++) {
            float v = s[o];
            #pragma unroll
            for (int off = 16; off; off >>= 1)
                v += __shfl_xor_sync(0xffffffffu, v, off);
            if (lane == 0)
                g_feat[img * 64 + og * 8 + o] = fmaxf(v + fcb[og * 8 + o], 0.f);
        }
    }
}

// =========================================================================
// Kernel 4: Eq3to3 + relu + mean(ijk), factorized through Abar.
// fp32x2 packed GEMM core, [d][k]-transposed activations, 2 blocks/SM.
// =========================================================================
#define EQ_SMEM ((2304 + 64 + 3*4352 + 2*2048 + 64 + 2048) * 4)
__global__ __launch_bounds__(256, 2) void eq_kernel(
    const float* __restrict__ eqw, const float* __restrict__ eqb)
{
    extern __shared__ float sm[];
    float* sat  = sm;            // [d][k] pad 36 : 2304
    float* sAb  = sat + 2304;    // 64
    float* sV   = sAb + 64;      // [d][e] pad 68 : 4352
    float* sCk  = sV  + 4352;
    float* sCj  = sCk + 4352;
    float* sgk  = sCj + 4352;    // [k][e] : 2048
    float* sgj  = sgk + 2048;    // [j][e] : 2048
    float* ssb  = sgj + 2048;    // 64
    float* sred = ssb + 64;      // 2048

    const int b   = blockIdx.x >> 5;
    const int ii  = blockIdx.x & 31;
    const int tid = threadIdx.x;

    const float* fb = g_feat + b * KK * HID;
    for (int idx = tid; idx < 2048; idx += 256) {
        int k = idx >> 6, d = idx & 63;
        sat[d * 36 + k] = fb[idx];
    }
    __syncthreads();
    if (tid < 64) {
        const float* row = sat + tid * 36;
        float s = 0.f;
        #pragma unroll
        for (int k = 0; k < 32; k++) s += row[k];
        sAb[tid] = s * (1.0f / 32.0f);
    }
    __syncthreads();

    for (int idx = tid; idx < 4096; idx += 256) {
        int d = idx >> 6, e = idx & 63;
        const float4* wp = (const float4*)(eqw + (size_t)idx * 8);
        float4 wA = wp[0];   // w0 w1 w2 w3
        float4 wB = wp[1];   // w4 w5 w6 w7
        float ai = sat[d * 36 + ii], ab = sAb[d];
        sV [d * 68 + e] = wA.x * ai + wA.y * ab;
        sCk[d * 68 + e] = ab * (wA.z * ai + wB.x * ab);
        sCj[d * 68 + e] = ab * (wA.w * ai + wB.y * ab);
    }
    if (tid < 64) {
        int e = tid;
        float s = 0.f;
        for (int d = 0; d < 64; d++) {
            float ab = sAb[d];
            float2 w67 = *(const float2*)(eqw + ((size_t)(d * 64 + e)) * 8 + 6);
            s += ab * ab * (w67.x * sat[d * 36 + ii] + w67.y * ab);
        }
        ssb[e] = s + eqb[e];
    }
    __syncthreads();

    for (int idx = tid; idx < 2048; idx += 256) {
        int k = idx >> 6, e = idx & 63;
        float s1 = 0.f, s2 = 0.f;
        #pragma unroll 8
        for (int d = 0; d < 64; d++) {
            float ak = sat[d * 36 + k];
            s1 += sCk[d * 68 + e] * ak;
            s2 += sCj[d * 68 + e] * ak;
        }
        sgk[k * 64 + e] = s1;
        sgj[k * 64 + e] = s2;
    }
    __syncthreads();

    const int eg  = tid & 7;        // 8 e-groups of 8
    const int jkg = tid >> 3;       // 32 jk-groups of 8

    float esum[8];
    #pragma unroll
    for (int v = 0; v < 8; v++) esum[v] = 0.f;

    for (int pass = 0; pass < 4; pass++) {
        const int j  = pass * 8 + (jkg >> 2);
        const int k0 = (jkg & 3) * 8;

        u64 acc2[8][4];
        #pragma unroll
        for (int u = 0; u < 8; u++)
            #pragma unroll
            for (int v = 0; v < 4; v++) acc2[u][v] = 0ull;

        for (int d = 0; d < 64; d++) {
            const float* rowd = sat + d * 36;
            float aj = rowd[j];
            float4 ka = *(const float4*)(rowd + k0);
            float4 kb = *(const float4*)(rowd + k0 + 4);
            ulonglong2 V0 = *(const ulonglong2*)(sV + d * 68 + eg * 8);
            ulonglong2 V1 = *(const ulonglong2*)(sV + d * 68 + eg * 8 + 4);
            u64 Vv[4] = {V0.x, V0.y, V1.x, V1.y};
            float akf[8] = {ka.x, ka.y, ka.z, ka.w, kb.x, kb.y, kb.z, kb.w};
            #pragma unroll
            for (int u = 0; u < 8; u++) {
                float pr = aj * akf[u];
                u64 prd = pack2(pr, pr);
                acc2[u][0] = ffma2(prd, Vv[0], acc2[u][0]);
                acc2[u][1] = ffma2(prd, Vv[1], acc2[u][1]);
                acc2[u][2] = ffma2(prd, Vv[2], acc2[u][2]);
                acc2[u][3] = ffma2(prd, Vv[3], acc2[u][3]);
            }
        }

        const float* gjp = sgj + j * 64 + eg * 8;
        const float* sbp = ssb + eg * 8;
        #pragma unroll
        for (int u = 0; u < 8; u++) {
            const float* gkp = sgk + (k0 + u) * 64 + eg * 8;
            #pragma unroll
            for (int v2 = 0; v2 < 4; v2++) {
                float a0, a1;
                unpack2(acc2[u][v2], a0, a1);
                float v0 = a0 + gjp[2 * v2]     + gkp[2 * v2]     + sbp[2 * v2];
                float v1 = a1 + gjp[2 * v2 + 1] + gkp[2 * v2 + 1] + sbp[2 * v2 + 1];
                esum[2 * v2]     += fmaxf(v0, 0.f);
                esum[2 * v2 + 1] += fmaxf(v1, 0.f);
            }
        }
    }

    #pragma unroll
    for (int v = 0; v < 8; v++) sred[jkg * 64 + eg * 8 + v] = esum[v];
    __syncthreads();
    if (tid < 64) {
        float s = 0.f;
        #pragma unroll
        for (int g = 0; g < 32; g++) s += sred[g * 64 + tid];
        g_part[blockIdx.x * 64 + tid] = s;
    }
}

// =========================================================================
// Kernel 5: final
// =========================================================================
__global__ __launch_bounds__(64) void final_kernel(
    const float* __restrict__ outw, const float* __restrict__ outb,
    float* __restrict__ out)
{
    __shared__ float red[64];
    const int b = blockIdx.x, e = threadIdx.x;
    float s = 0.f;
    #pragma unroll
    for (int i = 0; i < 32; i++) s += g_part[(b * 32 + i) * 64 + e];
    float x8 = s * (1.0f / 32768.0f);
    red[e] = fmaxf(x8, 0.f) * outw[e];
    __syncthreads();
    #pragma unroll
    for (int off = 32; off; off >>= 1) {
        if (e < off) red[e] += red[e + off];
        __syncthreads();
    }
    if (e == 0) out[b] = red[0] + outb[0];
}

// =========================================================================
extern "C" void kernel_launch(void* const* d_in, const int* in_sizes, int n_in,
                              void* d_out, int out_size)
{
    const float* x    = (const float*)d_in[0];
    const float* c1w  = (const float*)d_in[1];
    const float* c1b  = (const float*)d_in[2];
    const float* c2w  = (const float*)d_in[3];
    const float* c2b  = (const float*)d_in[4];
    const float* fcw  = (const float*)d_in[5];
    const float* fcb  = (const float*)d_in[6];
    const float* eqw  = (const float*)d_in[7];
    const float* eqb  = (const float*)d_in[8];
    const float* outw = (const float*)d_in[9];
    const float* outb = (const float*)d_in[10];
    float* out = (float*)d_out;

    cudaFuncSetAttribute(conv2_kernel, cudaFuncAttributeMaxDynamicSharedMemorySize, CONV2_SMEM);
    cudaFuncSetAttribute(eq_kernel,    cudaFuncAttributeMaxDynamicSharedMemorySize, EQ_SMEM);

    conv1_kernel<<<NIMG, 256>>>(x, c1w, c1b);
    conv2_kernel<<<NIMG, 256, CONV2_SMEM>>>(c2w, c2b);
    fc_kernel<<<64, 256>>>(fcw, fcb);
    eq_kernel<<<NIMG, 256, EQ_SMEM>>>(eqw, eqb);
    final_kernel<<<BB, 64>>>(outw, outb, out);
}

// round 4
// speedup vs baseline: 1.7628x; 1.0589x over previous
#include <cuda_runtime.h>
#include <cuda_bf16.h>
#include <math.h>

#define BB   16
#define KK   32
#define HH   28
#define WW   28
#define HID  64
#define OUT  64
#define NIMG (BB*KK)          // 512

typedef unsigned long long u64;

// ---------------- scratch ----------------
__device__ float g_h1[NIMG * 32 * 14 * 14];
__device__ float g_h2[NIMG * 64 * 7 * 7];
__device__ float g_feat[NIMG * HID];
__device__ float g_part[NIMG * OUT];

// ---------------- packed fp32x2 helpers ----------------
__device__ __forceinline__ u64 pack2(float x, float y) {
    u64 r; asm("mov.b64 %0,{%1,%2};" : "=l"(r) : "f"(x), "f"(y)); return r;
}
__device__ __forceinline__ void unpack2(u64 p, float& x, float& y) {
    asm("mov.b64 {%0,%1},%2;" : "=f"(x), "=f"(y) : "l"(p));
}
__device__ __forceinline__ u64 ffma2(u64 a, u64 b, u64 c) {
    u64 d; asm("fma.rn.f32x2 %0,%1,%2,%3;" : "=l"(d) : "l"(a), "l"(b), "l"(c)); return d;
}

// =========================================================================
// Kernel 1: conv1 (1->32, 3x3 SAME) + relu + maxpool2
// =========================================================================
__global__ __launch_bounds__(256) void conv1_kernel(
    const float* __restrict__ x, const float* __restrict__ w,
    const float* __restrict__ bias)
{
    __shared__ float sin1[30 * 30];
    __shared__ float sw1[32 * 9];
    __shared__ float sb1[32];

    const int img = blockIdx.x;
    const int tid = threadIdx.x;

    for (int i = tid; i < 900; i += 256) sin1[i] = 0.f;
    for (int i = tid; i < 288; i += 256) sw1[i] = w[i];
    if (tid < 32) sb1[tid] = bias[tid];
    __syncthreads();
    for (int i = tid; i < 784; i += 256) {
        int y = i / 28, xx = i % 28;
        sin1[(y + 1) * 30 + xx + 1] = x[img * 784 + i];
    }
    __syncthreads();

    for (int item = tid; item < 32 * 196; item += 256) {
        int c = item / 196, p = item % 196;
        int oy = p / 14, ox = p % 14;
        const float* wp = sw1 + c * 9;
        const float bv = sb1[c];
        float m = 0.f;
        #pragma unroll
        for (int py = 0; py < 2; py++) {
            #pragma unroll
            for (int px = 0; px < 2; px++) {
                int r = 2 * oy + py, col = 2 * ox + px;
                float s = bv;
                #pragma unroll
                for (int ky = 0; ky < 3; ky++)
                    #pragma unroll
                    for (int kx = 0; kx < 3; kx++)
                        s += sin1[(r + ky) * 30 + col + kx] * wp[ky * 3 + kx];
                m = fmaxf(m, s);
            }
        }
        g_h1[img * (32 * 196) + item] = m;
    }
}

// =========================================================================
// Kernel 2: conv2 (32->64) + relu + maxpool2, fp32x2 packed FMA.
// launch_bounds(256,2): cap regs at 128 -> 2 blocks/SM (smem 105KB x2).
// =========================================================================
#define CONV2_SMEM ((8192 + 18432 + 64) * 4)
__global__ __launch_bounds__(256, 2) void conv2_kernel(
    const float* __restrict__ w, const float* __restrict__ bias)
{
    extern __shared__ float sm2[];
    float* sin2 = sm2;                 // 32 * 16*16
    float* sw2  = sm2 + 8192;          // [ic*9+r][c] : 288*64
    float* sb2  = sw2 + 18432;

    const int img = blockIdx.x;
    const int tid = threadIdx.x;

    for (int i = tid; i < 8192; i += 256) sin2[i] = 0.f;
    for (int idx = tid; idx < 18432; idx += 256) {
        int f = idx >> 6, c = idx & 63;
        int ic = f / 9, r = f % 9;
        sw2[idx] = w[(c * 32 + ic) * 9 + r];
    }
    if (tid < 64) sb2[tid] = bias[tid];
    __syncthreads();
    for (int i = tid; i < 32 * 196; i += 256) {
        int ic = i / 196, p = i % 196;
        int y = p / 14, xx = p % 14;
        sin2[ic * 256 + (y + 1) * 16 + xx + 1] = g_h1[img * (32 * 196) + i];
    }
    __syncthreads();

    if (tid < 196) {
        const int cg  = tid / 49;
        const int pos = tid % 49;
        const int oy = pos / 7, ox = pos % 7;
        const int c0 = cg * 16;
        const int iy = 2 * oy, ix = 2 * ox;

        u64 acc2[4][8];
        #pragma unroll
        for (int p = 0; p < 4; p++)
            #pragma unroll
            for (int q = 0; q < 8; q++) acc2[p][q] = 0ull;

        for (int ic = 0; ic < 32; ic++) {
            const float* ip = sin2 + ic * 256;
            #pragma unroll
            for (int ky = 0; ky < 3; ky++) {
                const float* r0 = ip + (iy + ky) * 16 + ix;
                const float* r1 = r0 + 16;
                #pragma unroll
                for (int kx = 0; kx < 3; kx++) {
                    u64 d00 = pack2(r0[kx],     r0[kx]);
                    u64 d01 = pack2(r0[kx + 1], r0[kx + 1]);
                    u64 d10 = pack2(r1[kx],     r1[kx]);
                    u64 d11 = pack2(r1[kx + 1], r1[kx + 1]);
                    const float* wp = sw2 + ((ic * 3 + ky) * 3 + kx) * 64 + c0;
                    ulonglong2 wA = *(const ulonglong2*)(wp);
                    ulonglong2 wB = *(const ulonglong2*)(wp + 4);
                    ulonglong2 wC = *(const ulonglong2*)(wp + 8);
                    ulonglong2 wD = *(const ulonglong2*)(wp + 12);
                    u64 wv[8] = {wA.x, wA.y, wB.x, wB.y, wC.x, wC.y, wD.x, wD.y};
                    #pragma unroll
                    for (int q = 0; q < 8; q++) {
                        acc2[0][q] = ffma2(d00, wv[q], acc2[0][q]);
                        acc2[1][q] = ffma2(d01, wv[q], acc2[1][q]);
                        acc2[2][q] = ffma2(d10, wv[q], acc2[2][q]);
                        acc2[3][q] = ffma2(d11, wv[q], acc2[3][q]);
                    }
                }
            }
        }
        #pragma unroll
        for (int q = 0; q < 8; q++) {
            float a0[4], a1[4];
            #pragma unroll
            for (int p = 0; p < 4; p++) unpack2(acc2[p][q], a0[p], a1[p]);
            float b0 = sb2[c0 + 2 * q], b1 = sb2[c0 + 2 * q + 1];
            float m0 = fmaxf(fmaxf(a0[0], a0[1]), fmaxf(a0[2], a0[3])) + b0;
            float m1 = fmaxf(fmaxf(a1[0], a1[1]), fmaxf(a1[2], a1[3])) + b1;
            g_h2[img * 3136 + (c0 + 2 * q) * 49 + pos]     = fmaxf(m0, 0.f);
            g_h2[img * 3136 + (c0 + 2 * q + 1) * 49 + pos] = fmaxf(m1, 0.f);
        }
    }
}

// =========================================================================
// Kernel 3: fc, weight-stationary. 64 blocks x 8 images.
// acts staged in smem; fc_w staged in transposed [i][o] chunks shared by
// all 8 images (weight L2 traffic 410MB -> 51MB).
// =========================================================================
#define FC_CHUNK 392
#define FC_WPAD  66
#define FC_SMEM  ((8 * 3136 + FC_CHUNK * FC_WPAD) * 4)
__global__ __launch_bounds__(256) void fc_kernel(
    const float* __restrict__ fcw, const float* __restrict__ fcb)
{
    extern __shared__ float smf[];
    float* sact = smf;                  // [8][3136]
    float* swc  = smf + 8 * 3136;       // [392][66] transposed chunk

    const int tid  = threadIdx.x;
    const int img0 = blockIdx.x * 8;

    for (int idx = tid; idx < 8 * 3136; idx += 256)
        sact[idx] = g_h2[img0 * 3136 + idx];

    const int o2 = (tid & 31) * 2;
    const int q  = tid >> 5;             // 0..7 : i-slice within chunk

    u64 acc[8];
    #pragma unroll
    for (int im = 0; im < 8; im++) acc[im] = 0ull;

    for (int ch = 0; ch < 8; ch++) {
        __syncthreads();
        for (int idx = tid; idx < 64 * FC_CHUNK; idx += 256) {
            int o = idx / FC_CHUNK, i = idx % FC_CHUNK;
            swc[i * FC_WPAD + o] = fcw[(size_t)o * 3136 + ch * FC_CHUNK + i];
        }
        __syncthreads();

        const int ibase = q * 49;
        #pragma unroll 7
        for (int t = 0; t < 49; t++) {
            int i = ibase + t;
            u64 wv = *(const u64*)(swc + i * FC_WPAD + o2);
            int gi = ch * FC_CHUNK + i;
            #pragma unroll
            for (int im = 0; im < 8; im++) {
                float a = sact[im * 3136 + gi];
                acc[im] = ffma2(pack2(a, a), wv, acc[im]);
            }
        }
    }
    __syncthreads();

    // reduce over q via smem (reuse weight area): [q][img][64]
    float* sred = swc;
    #pragma unroll
    for (int im = 0; im < 8; im++) {
        float a0, a1;
        unpack2(acc[im], a0, a1);
        sred[q * 512 + im * 64 + o2]     = a0;
        sred[q * 512 + im * 64 + o2 + 1] = a1;
    }
    __syncthreads();
    for (int idx = tid; idx < 512; idx += 256) {
        int im = idx >> 6, o = idx & 63;
        float s = 0.f;
        #pragma unroll
        for (int qq = 0; qq < 8; qq++) s += sred[qq * 512 + idx];
        g_feat[(img0 + im) * 64 + o] = fmaxf(s + fcb[o], 0.f);
    }
}

// =========================================================================
// Kernel 4: Eq3to3 + relu + mean(ijk). fp32x2 GEMM core with software-
// pipelined d-loop (prefetch d+1 while computing d).
// =========================================================================
#define EQ_SMEM ((2304 + 64 + 3*4352 + 2*2048 + 64 + 2048) * 4)
__global__ __launch_bounds__(256, 2) void eq_kernel(
    const float* __restrict__ eqw, const float* __restrict__ eqb)
{
    extern __shared__ float sm[];
    float* sat  = sm;            // [d][k] pad 36 : 2304
    float* sAb  = sat + 2304;    // 64
    float* sV   = sAb + 64;      // [d][e] pad 68 : 4352
    float* sCk  = sV  + 4352;
    float* sCj  = sCk + 4352;
    float* sgk  = sCj + 4352;    // [k][e] : 2048
    float* sgj  = sgk + 2048;    // [j][e] : 2048
    float* ssb  = sgj + 2048;    // 64
    float* sred = ssb + 64;      // 2048

    const int b   = blockIdx.x >> 5;
    const int ii  = blockIdx.x & 31;
    const int tid = threadIdx.x;

    const float* fb = g_feat + b * KK * HID;
    for (int idx = tid; idx < 2048; idx += 256) {
        int k = idx >> 6, d = idx & 63;
        sat[d * 36 + k] = fb[idx];
    }
    __syncthreads();
    if (tid < 64) {
        const float* row = sat + tid * 36;
        float s = 0.f;
        #pragma unroll
        for (int k = 0; k < 32; k++) s += row[k];
        sAb[tid] = s * (1.0f / 32.0f);
    }
    __syncthreads();

    for (int idx = tid; idx < 4096; idx += 256) {
        int d = idx >> 6, e = idx & 63;
        const float4* wp = (const float4*)(eqw + (size_t)idx * 8);
        float4 wA = wp[0];
        float4 wB = wp[1];
        float ai = sat[d * 36 + ii], ab = sAb[d];
        sV [d * 68 + e] = wA.x * ai + wA.y * ab;
        sCk[d * 68 + e] = ab * (wA.z * ai + wB.x * ab);
        sCj[d * 68 + e] = ab * (wA.w * ai + wB.y * ab);
    }
    if (tid < 64) {
        int e = tid;
        float s = 0.f;
        for (int d = 0; d < 64; d++) {
            float ab = sAb[d];
            float2 w67 = *(const float2*)(eqw + ((size_t)(d * 64 + e)) * 8 + 6);
            s += ab * ab * (w67.x * sat[d * 36 + ii] + w67.y * ab);
        }
        ssb[e] = s + eqb[e];
    }
    __syncthreads();

    for (int idx = tid; idx < 2048; idx += 256) {
        int k = idx >> 6, e = idx & 63;
        float s1 = 0.f, s2 = 0.f;
        #pragma unroll 8
        for (int d = 0; d < 64; d++) {
            float ak = sat[d * 36 + k];
            s1 += sCk[d * 68 + e] * ak;
            s2 += sCj[d * 68 + e] * ak;
        }
        sgk[k * 64 + e] = s1;
        sgj[k * 64 + e] = s2;
    }
    __syncthreads();

    const int eg  = tid & 7;
    const int jkg = tid >> 3;

    float esum[8];
    #pragma unroll
    for (int v = 0; v < 8; v++) esum[v] = 0.f;

    for (int pass = 0; pass < 4; pass++) {
        const int j  = pass * 8 + (jkg >> 2);
        const int k0 = (jkg & 3) * 8;

        u64 acc2[8][4];
        #pragma unroll
        for (int u = 0; u < 8; u++)
            #pragma unroll
            for (int v = 0; v < 4; v++) acc2[u][v] = 0ull;

        // software-pipelined d-loop
        float       ajn = sat[j];
        float4      kan = *(const float4*)(sat + k0);
        float4      kbn = *(const float4*)(sat + k0 + 4);
        ulonglong2  V0n = *(const ulonglong2*)(sV + eg * 8);
        ulonglong2  V1n = *(const ulonglong2*)(sV + eg * 8 + 4);

        #pragma unroll 4
        for (int d = 0; d < 64; d++) {
            float      aj = ajn;
            float4     ka = kan, kb = kbn;
            ulonglong2 V0 = V0n, V1 = V1n;
            if (d < 63) {
                const float* rn = sat + (d + 1) * 36;
                ajn = rn[j];
                kan = *(const float4*)(rn + k0);
                kbn = *(const float4*)(rn + k0 + 4);
                V0n = *(const ulonglong2*)(sV + (d + 1) * 68 + eg * 8);
                V1n = *(const ulonglong2*)(sV + (d + 1) * 68 + eg * 8 + 4);
            }
            u64 Vv[4] = {V0.x, V0.y, V1.x, V1.y};
            float akf[8] = {ka.x, ka.y, ka.z, ka.w, kb.x, kb.y, kb.z, kb.w};
            #pragma unroll
            for (int u = 0; u < 8; u++) {
                float pr = aj * akf[u];
                u64 prd = pack2(pr, pr);
                acc2[u][0] = ffma2(prd, Vv[0], acc2[u][0]);
                acc2[u][1] = ffma2(prd, Vv[1], acc2[u][1]);
                acc2[u][2] = ffma2(prd, Vv[2], acc2[u][2]);
                acc2[u][3] = ffma2(prd, Vv[3], acc2[u][3]);
            }
        }

        const float* gjp = sgj + j * 64 + eg * 8;
        const float* sbp = ssb + eg * 8;
        #pragma unroll
        for (int u = 0; u < 8; u++) {
            const float* gkp = sgk + (k0 + u) * 64 + eg * 8;
            #pragma unroll
            for (int v2 = 0; v2 < 4; v2++) {
                float a0, a1;
                unpack2(acc2[u][v2], a0, a1);
                float v0 = a0 + gjp[2 * v2]     + gkp[2 * v2]     + sbp[2 * v2];
                float v1 = a1 + gjp[2 * v2 + 1] + gkp[2 * v2 + 1] + sbp[2 * v2 + 1];
                esum[2 * v2]     += fmaxf(v0, 0.f);
                esum[2 * v2 + 1] += fmaxf(v1, 0.f);
            }
        }
    }

    #pragma unroll
    for (int v = 0; v < 8; v++) sred[jkg * 64 + eg * 8 + v] = esum[v];
    __syncthreads();
    if (tid < 64) {
        float s = 0.f;
        #pragma unroll
        for (int g = 0; g < 32; g++) s += sred[g * 64 + tid];
        g_part[blockIdx.x * 64 + tid] = s;
    }
}

// =========================================================================
// Kernel 5: final
// =========================================================================
__global__ __launch_bounds__(64) void final_kernel(
    const float* __restrict__ outw, const float* __restrict__ outb,
    float* __restrict__ out)
{
    __shared__ float red[64];
    const int b = blockIdx.x, e = threadIdx.x;
    float s = 0.f;
    #pragma unroll
    for (int i = 0; i < 32; i++) s += g_part[(b * 32 + i) * 64 + e];
    float x8 = s * (1.0f / 32768.0f);
    red[e] = fmaxf(x8, 0.f) * outw[e];
    __syncthreads();
    #pragma unroll
    for (int off = 32; off; off >>= 1) {
        if (e < off) red[e] += red[e + off];
        __syncthreads();
    }
    if (e == 0) out[b] = red[0] + outb[0];
}

// =========================================================================
extern "C" void kernel_launch(void* const* d_in, const int* in_sizes, int n_in,
                              void* d_out, int out_size)
{
    const float* x    = (const float*)d_in[0];
    const float* c1w  = (const float*)d_in[1];
    const float* c1b  = (const float*)d_in[2];
    const float* c2w  = (const float*)d_in[3];
    const float* c2b  = (const float*)d_in[4];
    const float* fcw  = (const float*)d_in[5];
    const float* fcb  = (const float*)d_in[6];
    const float* eqw  = (const float*)d_in[7];
    const float* eqb  = (const float*)d_in[8];
    const float* outw = (const float*)d_in[9];
    const float* outb = (const float*)d_in[10];
    float* out = (float*)d_out;

    cudaFuncSetAttribute(conv2_kernel, cudaFuncAttributeMaxDynamicSharedMemorySize, CONV2_SMEM);
    cudaFuncSetAttribute(fc_kernel,    cudaFuncAttributeMaxDynamicSharedMemorySize, FC_SMEM);
    cudaFuncSetAttribute(eq_kernel,    cudaFuncAttributeMaxDynamicSharedMemorySize, EQ_SMEM);

    conv1_kernel<<<NIMG, 256>>>(x, c1w, c1b);
    conv2_kernel<<<NIMG, 256, CONV2_SMEM>>>(c2w, c2b);
    fc_kernel<<<64, 256, FC_SMEM>>>(fcw, fcb);
    eq_kernel<<<NIMG, 256, EQ_SMEM>>>(eqw, eqb);
    final_kernel<<<BB, 64>>>(outw, outb, out);
}

// round 5
// speedup vs baseline: 1.9155x; 1.0866x over previous
#include <cuda_runtime.h>
#include <cuda_bf16.h>
#include <math.h>

#define BB   16
#define KK   32
#define HH   28
#define WW   28
#define HID  64
#define OUT  64
#define NIMG (BB*KK)          // 512

typedef unsigned long long u64;

// ---------------- scratch ----------------
__device__ float g_h1[NIMG * 32 * 14 * 14];
__device__ float g_h2[NIMG * 64 * 7 * 7];
__device__ float g_feat[NIMG * HID];
__device__ float g_part[NIMG * OUT];

// ---------------- packed fp32x2 helpers ----------------
__device__ __forceinline__ u64 pack2(float x, float y) {
    u64 r; asm("mov.b64 %0,{%1,%2};" : "=l"(r) : "f"(x), "f"(y)); return r;
}
__device__ __forceinline__ void unpack2(u64 p, float& x, float& y) {
    asm("mov.b64 {%0,%1},%2;" : "=f"(x), "=f"(y) : "l"(p));
}
__device__ __forceinline__ u64 ffma2(u64 a, u64 b, u64 c) {
    u64 d; asm("fma.rn.f32x2 %0,%1,%2,%3;" : "=l"(d) : "l"(a), "l"(b), "l"(c)); return d;
}

// =========================================================================
// Kernel 1: conv1 (1->32, 3x3 SAME) + relu + maxpool2
// =========================================================================
__global__ __launch_bounds__(256) void conv1_kernel(
    const float* __restrict__ x, const float* __restrict__ w,
    const float* __restrict__ bias)
{
    __shared__ float sin1[30 * 30];
    __shared__ float sw1[32 * 9];
    __shared__ float sb1[32];

    const int img = blockIdx.x;
    const int tid = threadIdx.x;

    for (int i = tid; i < 900; i += 256) sin1[i] = 0.f;
    for (int i = tid; i < 288; i += 256) sw1[i] = w[i];
    if (tid < 32) sb1[tid] = bias[tid];
    __syncthreads();
    for (int i = tid; i < 784; i += 256) {
        int y = i / 28, xx = i % 28;
        sin1[(y + 1) * 30 + xx + 1] = x[img * 784 + i];
    }
    __syncthreads();

    for (int item = tid; item < 32 * 196; item += 256) {
        int c = item / 196, p = item % 196;
        int oy = p / 14, ox = p % 14;
        const float* wp = sw1 + c * 9;
        const float bv = sb1[c];
        float m = 0.f;
        #pragma unroll
        for (int py = 0; py < 2; py++) {
            #pragma unroll
            for (int px = 0; px < 2; px++) {
                int r = 2 * oy + py, col = 2 * ox + px;
                float s = bv;
                #pragma unroll
                for (int ky = 0; ky < 3; ky++)
                    #pragma unroll
                    for (int kx = 0; kx < 3; kx++)
                        s += sin1[(r + ky) * 30 + col + kx] * wp[ky * 3 + kx];
                m = fmaxf(m, s);
            }
        }
        g_h1[img * (32 * 196) + item] = m;
    }
}

// =========================================================================
// Kernel 2: conv2 (32->64) + relu + maxpool2, fp32x2 packed FMA.
// 392 threads: thread = (cg of 8 out-channels, pool pos). Input 4x4 patch
// register-cached per ic. launch_bounds(392,2) -> 26 warps/SM.
// =========================================================================
#define CONV2_SMEM ((8192 + 18432 + 64) * 4)
__global__ __launch_bounds__(392, 2) void conv2_kernel(
    const float* __restrict__ w, const float* __restrict__ bias)
{
    extern __shared__ float sm2[];
    float* sin2 = sm2;                 // 32 * 16*16 (zero-padded)
    float* sw2  = sm2 + 8192;          // [ic*9+r][c] : 288*64
    float* sb2  = sw2 + 18432;

    const int img = blockIdx.x;
    const int tid = threadIdx.x;
    const int nt  = blockDim.x;        // 392

    for (int i = tid; i < 8192; i += nt) sin2[i] = 0.f;
    for (int idx = tid; idx < 18432; idx += nt) {
        int f = idx >> 6, c = idx & 63;
        int ic = f / 9, r = f % 9;
        sw2[idx] = w[(c * 32 + ic) * 9 + r];
    }
    if (tid < 64) sb2[tid] = bias[tid];
    __syncthreads();
    for (int i = tid; i < 32 * 196; i += nt) {
        int ic = i / 196, p = i % 196;
        int y = p / 14, xx = p % 14;
        sin2[ic * 256 + (y + 1) * 16 + xx + 1] = g_h1[img * (32 * 196) + i];
    }
    __syncthreads();

    {
        const int cg  = tid / 49;      // 8 groups of 8 channels
        const int pos = tid % 49;
        const int oy = pos / 7, ox = pos % 7;
        const int c0 = cg * 8;
        const int iy = 2 * oy, ix = 2 * ox;

        u64 acc2[4][4];                // [pool window][ch-pair]
        #pragma unroll
        for (int p = 0; p < 4; p++)
            #pragma unroll
            for (int q = 0; q < 4; q++) acc2[p][q] = 0ull;

        for (int ic = 0; ic < 32; ic++) {
            const float* ip = sin2 + ic * 256;
            float patch[4][4];
            #pragma unroll
            for (int r = 0; r < 4; r++) {
                float2 p0 = *(const float2*)(ip + (iy + r) * 16 + ix);
                float2 p1 = *(const float2*)(ip + (iy + r) * 16 + ix + 2);
                patch[r][0] = p0.x; patch[r][1] = p0.y;
                patch[r][2] = p1.x; patch[r][3] = p1.y;
            }
            #pragma unroll
            for (int ky = 0; ky < 3; ky++) {
                #pragma unroll
                for (int kx = 0; kx < 3; kx++) {
                    const float* wp = sw2 + ((ic * 3 + ky) * 3 + kx) * 64 + c0;
                    ulonglong2 wA = *(const ulonglong2*)(wp);
                    ulonglong2 wB = *(const ulonglong2*)(wp + 4);
                    u64 wv[4] = {wA.x, wA.y, wB.x, wB.y};
                    u64 d00 = pack2(patch[ky][kx],     patch[ky][kx]);
                    u64 d01 = pack2(patch[ky][kx + 1], patch[ky][kx + 1]);
                    u64 d10 = pack2(patch[ky + 1][kx],     patch[ky + 1][kx]);
                    u64 d11 = pack2(patch[ky + 1][kx + 1], patch[ky + 1][kx + 1]);
                    #pragma unroll
                    for (int q = 0; q < 4; q++) {
                        acc2[0][q] = ffma2(d00, wv[q], acc2[0][q]);
                        acc2[1][q] = ffma2(d01, wv[q], acc2[1][q]);
                        acc2[2][q] = ffma2(d10, wv[q], acc2[2][q]);
                        acc2[3][q] = ffma2(d11, wv[q], acc2[3][q]);
                    }
                }
            }
        }
        #pragma unroll
        for (int q = 0; q < 4; q++) {
            float a0[4], a1[4];
            #pragma unroll
            for (int p = 0; p < 4; p++) unpack2(acc2[p][q], a0[p], a1[p]);
            float b0 = sb2[c0 + 2 * q], b1 = sb2[c0 + 2 * q + 1];
            float m0 = fmaxf(fmaxf(a0[0], a0[1]), fmaxf(a0[2], a0[3])) + b0;
            float m1 = fmaxf(fmaxf(a1[0], a1[1]), fmaxf(a1[2], a1[3])) + b1;
            g_h2[img * 3136 + (c0 + 2 * q) * 49 + pos]     = fmaxf(m0, 0.f);
            g_h2[img * 3136 + (c0 + 2 * q + 1) * 49 + pos] = fmaxf(m1, 0.f);
        }
    }
}

// =========================================================================
// Kernel 3: fc, weight-stationary. 64 blocks x 8 images.
// =========================================================================
#define FC_CHUNK 392
#define FC_WPAD  66
#define FC_SMEM  ((8 * 3136 + FC_CHUNK * FC_WPAD) * 4)
__global__ __launch_bounds__(256) void fc_kernel(
    const float* __restrict__ fcw, const float* __restrict__ fcb)
{
    extern __shared__ float smf[];
    float* sact = smf;                  // [8][3136]
    float* swc  = smf + 8 * 3136;       // [392][66] transposed chunk

    const int tid  = threadIdx.x;
    const int img0 = blockIdx.x * 8;

    for (int idx = tid; idx < 8 * 3136; idx += 256)
        sact[idx] = g_h2[img0 * 3136 + idx];

    const int o2 = (tid & 31) * 2;
    const int q  = tid >> 5;

    u64 acc[8];
    #pragma unroll
    for (int im = 0; im < 8; im++) acc[im] = 0ull;

    for (int ch = 0; ch < 8; ch++) {
        __syncthreads();
        for (int idx = tid; idx < 64 * FC_CHUNK; idx += 256) {
            int o = idx / FC_CHUNK, i = idx % FC_CHUNK;
            swc[i * FC_WPAD + o] = fcw[(size_t)o * 3136 + ch * FC_CHUNK + i];
        }
        __syncthreads();

        const int ibase = q * 49;
        #pragma unroll 7
        for (int t = 0; t < 49; t++) {
            int i = ibase + t;
            u64 wv = *(const u64*)(swc + i * FC_WPAD + o2);
            int gi = ch * FC_CHUNK + i;
            #pragma unroll
            for (int im = 0; im < 8; im++) {
                float a = sact[im * 3136 + gi];
                acc[im] = ffma2(pack2(a, a), wv, acc[im]);
            }
        }
    }
    __syncthreads();

    float* sred = swc;
    #pragma unroll
    for (int im = 0; im < 8; im++) {
        float a0, a1;
        unpack2(acc[im], a0, a1);
        sred[q * 512 + im * 64 + o2]     = a0;
        sred[q * 512 + im * 64 + o2 + 1] = a1;
    }
    __syncthreads();
    for (int idx = tid; idx < 512; idx += 256) {
        int im = idx >> 6, o = idx & 63;
        float s = 0.f;
        #pragma unroll
        for (int qq = 0; qq < 8; qq++) s += sred[qq * 512 + idx];
        g_feat[(img0 + im) * 64 + o] = fmaxf(s + fcb[o], 0.f);
    }
}

// =========================================================================
// Kernel 4: Eq3to3 + relu + mean(ijk). j<->k symmetry: A(j,k) is symmetric,
// so compute only upper-triangle 8x8 tile-blocks (10 of 16); epilogue
// emits both orderings: relu(A+gj[j]+gk[k]) and relu(A+gj[k]+gk[j]).
// =========================================================================
#define EQ_SMEM ((2304 + 64 + 3*4352 + 2*2048 + 64 + 2048) * 4)
__global__ __launch_bounds__(256, 2) void eq_kernel(
    const float* __restrict__ eqw, const float* __restrict__ eqb)
{
    extern __shared__ float sm[];
    float* sat  = sm;            // [d][k] pad 36 : 2304
    float* sAb  = sat + 2304;    // 64
    float* sV   = sAb + 64;      // [d][e] pad 68 : 4352
    float* sCk  = sV  + 4352;
    float* sCj  = sCk + 4352;
    float* sgk  = sCj + 4352;    // [k][e] : 2048
    float* sgj  = sgk + 2048;    // [j][e] : 2048
    float* ssb  = sgj + 2048;    // 64
    float* sred = ssb + 64;      // 2048

    const int b   = blockIdx.x >> 5;
    const int ii  = blockIdx.x & 31;
    const int tid = threadIdx.x;

    const float* fb = g_feat + b * KK * HID;
    for (int idx = tid; idx < 2048; idx += 256) {
        int k = idx >> 6, d = idx & 63;
        sat[d * 36 + k] = fb[idx];
    }
    __syncthreads();
    if (tid < 64) {
        const float* row = sat + tid * 36;
        float s = 0.f;
        #pragma unroll
        for (int k = 0; k < 32; k++) s += row[k];
        sAb[tid] = s * (1.0f / 32.0f);
    }
    __syncthreads();

    for (int idx = tid; idx < 4096; idx += 256) {
        int d = idx >> 6, e = idx & 63;
        const float4* wp = (const float4*)(eqw + (size_t)idx * 8);
        float4 wA = wp[0];
        float4 wB = wp[1];
        float ai = sat[d * 36 + ii], ab = sAb[d];
        sV [d * 68 + e] = wA.x * ai + wA.y * ab;
        sCk[d * 68 + e] = ab * (wA.z * ai + wB.x * ab);
        sCj[d * 68 + e] = ab * (wA.w * ai + wB.y * ab);
    }
    if (tid < 64) {
        int e = tid;
        float s = 0.f;
        for (int d = 0; d < 64; d++) {
            float ab = sAb[d];
            float2 w67 = *(const float2*)(eqw + ((size_t)(d * 64 + e)) * 8 + 6);
            s += ab * ab * (w67.x * sat[d * 36 + ii] + w67.y * ab);
        }
        ssb[e] = s + eqb[e];
    }
    __syncthreads();

    for (int idx = tid; idx < 2048; idx += 256) {
        int k = idx >> 6, e = idx & 63;
        float s1 = 0.f, s2 = 0.f;
        #pragma unroll 8
        for (int d = 0; d < 64; d++) {
            float ak = sat[d * 36 + k];
            s1 += sCk[d * 68 + e] * ak;
            s2 += sCj[d * 68 + e] * ak;
        }
        sgk[k * 64 + e] = s1;
        sgj[k * 64 + e] = s2;
    }
    __syncthreads();

    const int eg   = tid & 7;
    const int jkg  = tid >> 3;
    const int slot = jkg >> 3;      // 0..3 (warp-pair uniform)
    const int jrow = jkg & 7;       // 0..7

    // upper-triangle tile-block map, 4-bit packed
    const u64 JT = 0x3221110000ull;
    const u64 KT = 0x3323213210ull;

    float esum[8];
    #pragma unroll
    for (int v = 0; v < 8; v++) esum[v] = 0.f;

    for (int pass = 0; pass < 3; pass++) {
        const int tb = pass * 4 + slot;
        if (tb >= 10) continue;     // 2 idle slots in pass 2 (warp-uniform)
        const int jt = (int)((JT >> (4 * tb)) & 15);
        const int kt = (int)((KT >> (4 * tb)) & 15);
        const int j  = jt * 8 + jrow;
        const int k0 = kt * 8;
        const bool diag = (jt == kt);

        u64 acc2[8][4];
        #pragma unroll
        for (int u = 0; u < 8; u++)
            #pragma unroll
            for (int v = 0; v < 4; v++) acc2[u][v] = 0ull;

        // software-pipelined d-loop
        float       ajn = sat[j];
        float4      kan = *(const float4*)(sat + k0);
        float4      kbn = *(const float4*)(sat + k0 + 4);
        ulonglong2  V0n = *(const ulonglong2*)(sV + eg * 8);
        ulonglong2  V1n = *(const ulonglong2*)(sV + eg * 8 + 4);

        #pragma unroll 4
        for (int d = 0; d < 64; d++) {
            float      aj = ajn;
            float4     ka = kan, kb = kbn;
            ulonglong2 V0 = V0n, V1 = V1n;
            if (d < 63) {
                const float* rn = sat + (d + 1) * 36;
                ajn = rn[j];
                kan = *(const float4*)(rn + k0);
                kbn = *(const float4*)(rn + k0 + 4);
                V0n = *(const ulonglong2*)(sV + (d + 1) * 68 + eg * 8);
                V1n = *(const ulonglong2*)(sV + (d + 1) * 68 + eg * 8 + 4);
            }
            u64 Vv[4] = {V0.x, V0.y, V1.x, V1.y};
            float akf[8] = {ka.x, ka.y, ka.z, ka.w, kb.x, kb.y, kb.z, kb.w};
            #pragma unroll
            for (int u = 0; u < 8; u++) {
                float pr = aj * akf[u];
                u64 prd = pack2(pr, pr);
                acc2[u][0] = ffma2(prd, Vv[0], acc2[u][0]);
                acc2[u][1] = ffma2(prd, Vv[1], acc2[u][1]);
                acc2[u][2] = ffma2(prd, Vv[2], acc2[u][2]);
                acc2[u][3] = ffma2(prd, Vv[3], acc2[u][3]);
            }
        }

        // epilogue: both orderings (j,k) and (k,j)
        const float* sbp  = ssb + eg * 8;
        const float* gj_j = sgj + j * 64 + eg * 8;   // gj[j]
        const float* gk_j = sgk + j * 64 + eg * 8;   // gk[j]
        float4 gjj0 = *(const float4*)(gj_j), gjj1 = *(const float4*)(gj_j + 4);
        float4 gkj0 = *(const float4*)(gk_j), gkj1 = *(const float4*)(gk_j + 4);
        float gjjv[8] = {gjj0.x, gjj0.y, gjj0.z, gjj0.w, gjj1.x, gjj1.y, gjj1.z, gjj1.w};
        float gkjv[8] = {gkj0.x, gkj0.y, gkj0.z, gkj0.w, gkj1.x, gkj1.y, gkj1.z, gkj1.w};

        #pragma unroll
        for (int u = 0; u < 8; u++) {
            const int k = k0 + u;
            const float* gk_k = sgk + k * 64 + eg * 8;
            const float* gj_k = sgj + k * 64 + eg * 8;
            float4 gkk0 = *(const float4*)(gk_k), gkk1 = *(const float4*)(gk_k + 4);
            float4 gjk0 = *(const float4*)(gj_k), gjk1 = *(const float4*)(gj_k + 4);
            float gkkv[8] = {gkk0.x, gkk0.y, gkk0.z, gkk0.w, gkk1.x, gkk1.y, gkk1.z, gkk1.w};
            float gjkv[8] = {gjk0.x, gjk0.y, gjk0.z, gjk0.w, gjk1.x, gjk1.y, gjk1.z, gjk1.w};

            const bool take1 = diag ? (k >= j) : true;   // ordering (j,k)
            const bool take2 = diag ? (k > j)  : true;   // ordering (k,j)

            #pragma unroll
            for (int v2 = 0; v2 < 4; v2++) {
                float a0, a1;
                unpack2(acc2[u][v2], a0, a1);
                float p0 = a0 + gjjv[2 * v2]     + gkkv[2 * v2]     + sbp[2 * v2];
                float p1 = a1 + gjjv[2 * v2 + 1] + gkkv[2 * v2 + 1] + sbp[2 * v2 + 1];
                float q0 = a0 + gjkv[2 * v2]     + gkjv[2 * v2]     + sbp[2 * v2];
                float q1 = a1 + gjkv[2 * v2 + 1] + gkjv[2 * v2 + 1] + sbp[2 * v2 + 1];
                if (take1) {
                    esum[2 * v2]     += fmaxf(p0, 0.f);
                    esum[2 * v2 + 1] += fmaxf(p1, 0.f);
                }
                if (take2) {
                    esum[2 * v2]     += fmaxf(q0, 0.f);
                    esum[2 * v2 + 1] += fmaxf(q1, 0.f);
                }
            }
        }
    }

    #pragma unroll
    for (int v = 0; v < 8; v++) sred[jkg * 64 + eg * 8 + v] = esum[v];
    __syncthreads();
    if (tid < 64) {
        float s = 0.f;
        #pragma unroll
        for (int g = 0; g < 32; g++) s += sred[g * 64 + tid];
        g_part[blockIdx.x * 64 + tid] = s;
    }
}

// =========================================================================
// Kernel 5: final
// =========================================================================
__global__ __launch_bounds__(64) void final_kernel(
    const float* __restrict__ outw, const float* __restrict__ outb,
    float* __restrict__ out)
{
    __shared__ float red[64];
    const int b = blockIdx.x, e = threadIdx.x;
    float s = 0.f;
    #pragma unroll
    for (int i = 0; i < 32; i++) s += g_part[(b * 32 + i) * 64 + e];
    float x8 = s * (1.0f / 32768.0f);
    red[e] = fmaxf(x8, 0.f) * outw[e];
    __syncthreads();
    #pragma unroll
    for (int off = 32; off; off >>= 1) {
        if (e < off) red[e] += red[e + off];
        __syncthreads();
    }
    if (e == 0) out[b] = red[0] + outb[0];
}

// =========================================================================
extern "C" void kernel_launch(void* const* d_in, const int* in_sizes, int n_in,
                              void* d_out, int out_size)
{
    const float* x    = (const float*)d_in[0];
    const float* c1w  = (const float*)d_in[1];
    const float* c1b  = (const float*)d_in[2];
    const float* c2w  = (const float*)d_in[3];
    const float* c2b  = (const float*)d_in[4];
    const float* fcw  = (const float*)d_in[5];
    const float* fcb  = (const float*)d_in[6];
    const float* eqw  = (const float*)d_in[7];
    const float* eqb  = (const float*)d_in[8];
    const float* outw = (const float*)d_in[9];
    const float* outb = (const float*)d_in[10];
    float* out = (float*)d_out;

    cudaFuncSetAttribute(conv2_kernel, cudaFuncAttributeMaxDynamicSharedMemorySize, CONV2_SMEM);
    cudaFuncSetAttribute(fc_kernel,    cudaFuncAttributeMaxDynamicSharedMemorySize, FC_SMEM);
    cudaFuncSetAttribute(eq_kernel,    cudaFuncAttributeMaxDynamicSharedMemorySize, EQ_SMEM);

    conv1_kernel<<<NIMG, 256>>>(x, c1w, c1b);
    conv2_kernel<<<NIMG, 392, CONV2_SMEM>>>(c2w, c2b);
    fc_kernel<<<64, 256, FC_SMEM>>>(fcw, fcb);
    eq_kernel<<<NIMG, 256, EQ_SMEM>>>(eqw, eqb);
    final_kernel<<<BB, 64>>>(outw, outb, out);
}

// round 6
// speedup vs baseline: 1.9314x; 1.0083x over previous
#include <cuda_runtime.h>
#include <cuda_bf16.h>
#include <math.h>

#define BB   16
#define KK   32
#define HH   28
#define WW   28
#define HID  64
#define OUT  64
#define NIMG (BB*KK)          // 512

typedef unsigned long long u64;

// ---------------- scratch ----------------
__device__ float g_h1[NIMG * 32 * 14 * 14];
__device__ float g_h2[NIMG * 64 * 7 * 7];
__device__ float g_feat[NIMG * HID];
__device__ float g_part[NIMG * OUT];

// ---------------- packed fp32x2 helpers ----------------
__device__ __forceinline__ u64 pack2(float x, float y) {
    u64 r; asm("mov.b64 %0,{%1,%2};" : "=l"(r) : "f"(x), "f"(y)); return r;
}
__device__ __forceinline__ void unpack2(u64 p, float& x, float& y) {
    asm("mov.b64 {%0,%1},%2;" : "=f"(x), "=f"(y) : "l"(p));
}
__device__ __forceinline__ u64 ffma2(u64 a, u64 b, u64 c) {
    u64 d; asm("fma.rn.f32x2 %0,%1,%2,%3;" : "=l"(d) : "l"(a), "l"(b), "l"(c)); return d;
}

// =========================================================================
// Kernel 1: conv1 (1->32, 3x3 SAME) + relu + maxpool2
// =========================================================================
__global__ __launch_bounds__(256) void conv1_kernel(
    const float* __restrict__ x, const float* __restrict__ w,
    const float* __restrict__ bias)
{
    __shared__ float sin1[30 * 30];
    __shared__ float sw1[32 * 9];
    __shared__ float sb1[32];

    const int img = blockIdx.x;
    const int tid = threadIdx.x;

    for (int i = tid; i < 900; i += 256) sin1[i] = 0.f;
    for (int i = tid; i < 288; i += 256) sw1[i] = w[i];
    if (tid < 32) sb1[tid] = bias[tid];
    __syncthreads();
    for (int i = tid; i < 784; i += 256) {
        int y = i / 28, xx = i % 28;
        sin1[(y + 1) * 30 + xx + 1] = x[img * 784 + i];
    }
    __syncthreads();

    for (int item = tid; item < 32 * 196; item += 256) {
        int c = item / 196, p = item % 196;
        int oy = p / 14, ox = p % 14;
        const float* wp = sw1 + c * 9;
        const float bv = sb1[c];
        float m = 0.f;
        #pragma unroll
        for (int py = 0; py < 2; py++) {
            #pragma unroll
            for (int px = 0; px < 2; px++) {
                int r = 2 * oy + py, col = 2 * ox + px;
                float s = bv;
                #pragma unroll
                for (int ky = 0; ky < 3; ky++)
                    #pragma unroll
                    for (int kx = 0; kx < 3; kx++)
                        s += sin1[(r + ky) * 30 + col + kx] * wp[ky * 3 + kx];
                m = fmaxf(m, s);
            }
        }
        g_h1[img * (32 * 196) + item] = m;
    }
}

// =========================================================================
// Kernel 2: conv2 (32->64) + relu + maxpool2, fp32x2 packed FMA.
// 256 threads, launch_bounds(256,2) -> 128 regs (no spills).
// Input in position-major smem [p][ic] with ic-stride 33 -> conflict-free
// patch loads. cg = tid>>6 -> warp-uniform channel group -> weight LDS
// is pure broadcast. Thread: 16 out-channels x 2x2 pool window.
// =========================================================================
#define C2_PPAD 33
#define CONV2_SMEM ((256 * C2_PPAD + 18432 + 64) * 4)
__global__ __launch_bounds__(256, 2) void conv2_kernel(
    const float* __restrict__ w, const float* __restrict__ bias)
{
    extern __shared__ float sm2[];
    float* sinP = sm2;                     // [256 pos][33] (zero-padded border)
    float* sw2  = sm2 + 256 * C2_PPAD;     // [ic*9+r][c] : 288*64
    float* sb2  = sw2 + 18432;

    const int img = blockIdx.x;
    const int tid = threadIdx.x;

    for (int i = tid; i < 256 * C2_PPAD; i += 256) sinP[i] = 0.f;
    for (int idx = tid; idx < 18432; idx += 256) {
        int f = idx >> 6, c = idx & 63;
        int ic = f / 9, r = f % 9;
        sw2[idx] = w[(c * 32 + ic) * 9 + r];
    }
    if (tid < 64) sb2[tid] = bias[tid];
    __syncthreads();
    for (int i = tid; i < 32 * 196; i += 256) {
        int ic = i / 196, p = i % 196;
        int y = p / 14, xx = p % 14;
        sinP[((y + 1) * 16 + xx + 1) * C2_PPAD + ic] = g_h1[img * (32 * 196) + i];
    }
    __syncthreads();

    {
        const int cg  = tid >> 6;          // warp-uniform: 4 groups of 16 ch
        const int pos = tid & 63;
        const int pp  = (pos < 49) ? pos : 0;
        const int oy = pp / 7, ox = pp % 7;
        const int c0 = cg * 16;
        const int iy = 2 * oy, ix = 2 * ox;

        u64 acc2[4][8];                    // [pool window][ch-pair]
        #pragma unroll
        for (int p = 0; p < 4; p++)
            #pragma unroll
            for (int q = 0; q < 8; q++) acc2[p][q] = 0ull;

        for (int ic = 0; ic < 32; ic++) {
            float patch[4][4];
            #pragma unroll
            for (int r = 0; r < 4; r++)
                #pragma unroll
                for (int cc = 0; cc < 4; cc++)
                    patch[r][cc] = sinP[((iy + r) * 16 + ix + cc) * C2_PPAD + ic];

            #pragma unroll
            for (int ky = 0; ky < 3; ky++) {
                #pragma unroll
                for (int kx = 0; kx < 3; kx++) {
                    const float* wp = sw2 + ((ic * 3 + ky) * 3 + kx) * 64 + c0;
                    ulonglong2 wA = *(const ulonglong2*)(wp);
                    ulonglong2 wB = *(const ulonglong2*)(wp + 4);
                    ulonglong2 wC = *(const ulonglong2*)(wp + 8);
                    ulonglong2 wD = *(const ulonglong2*)(wp + 12);
                    u64 wv[8] = {wA.x, wA.y, wB.x, wB.y, wC.x, wC.y, wD.x, wD.y};
                    u64 d00 = pack2(patch[ky][kx],         patch[ky][kx]);
                    u64 d01 = pack2(patch[ky][kx + 1],     patch[ky][kx + 1]);
                    u64 d10 = pack2(patch[ky + 1][kx],     patch[ky + 1][kx]);
                    u64 d11 = pack2(patch[ky + 1][kx + 1], patch[ky + 1][kx + 1]);
                    #pragma unroll
                    for (int q = 0; q < 8; q++) {
                        acc2[0][q] = ffma2(d00, wv[q], acc2[0][q]);
                        acc2[1][q] = ffma2(d01, wv[q], acc2[1][q]);
                        acc2[2][q] = ffma2(d10, wv[q], acc2[2][q]);
                        acc2[3][q] = ffma2(d11, wv[q], acc2[3][q]);
                    }
                }
            }
        }
        if (pos < 49) {
            #pragma unroll
            for (int q = 0; q < 8; q++) {
                float a0[4], a1[4];
                #pragma unroll
                for (int p = 0; p < 4; p++) unpack2(acc2[p][q], a0[p], a1[p]);
                float b0 = sb2[c0 + 2 * q], b1 = sb2[c0 + 2 * q + 1];
                float m0 = fmaxf(fmaxf(a0[0], a0[1]), fmaxf(a0[2], a0[3])) + b0;
                float m1 = fmaxf(fmaxf(a1[0], a1[1]), fmaxf(a1[2], a1[3])) + b1;
                g_h2[img * 3136 + (c0 + 2 * q) * 49 + pos]     = fmaxf(m0, 0.f);
                g_h2[img * 3136 + (c0 + 2 * q + 1) * 49 + pos] = fmaxf(m1, 0.f);
            }
        }
    }
}

// =========================================================================
// Kernel 3: fc, weight-stationary. 64 blocks x 8 images.
// =========================================================================
#define FC_CHUNK 392
#define FC_WPAD  66
#define FC_SMEM  ((8 * 3136 + FC_CHUNK * FC_WPAD) * 4)
__global__ __launch_bounds__(256) void fc_kernel(
    const float* __restrict__ fcw, const float* __restrict__ fcb)
{
    extern __shared__ float smf[];
    float* sact = smf;                  // [8][3136]
    float* swc  = smf + 8 * 3136;       // [392][66] transposed chunk

    const int tid  = threadIdx.x;
    const int img0 = blockIdx.x * 8;

    for (int idx = tid; idx < 8 * 3136; idx += 256)
        sact[idx] = g_h2[img0 * 3136 + idx];

    const int o2 = (tid & 31) * 2;
    const int q  = tid >> 5;

    u64 acc[8];
    #pragma unroll
    for (int im = 0; im < 8; im++) acc[im] = 0ull;

    for (int ch = 0; ch < 8; ch++) {
        __syncthreads();
        for (int idx = tid; idx < 64 * FC_CHUNK; idx += 256) {
            int o = idx / FC_CHUNK, i = idx % FC_CHUNK;
            swc[i * FC_WPAD + o] = fcw[(size_t)o * 3136 + ch * FC_CHUNK + i];
        }
        __syncthreads();

        const int ibase = q * 49;
        #pragma unroll 7
        for (int t = 0; t < 49; t++) {
            int i = ibase + t;
            u64 wv = *(const u64*)(swc + i * FC_WPAD + o2);
            int gi = ch * FC_CHUNK + i;
            #pragma unroll
            for (int im = 0; im < 8; im++) {
                float a = sact[im * 3136 + gi];
                acc[im] = ffma2(pack2(a, a), wv, acc[im]);
            }
        }
    }
    __syncthreads();

    float* sred = swc;
    #pragma unroll
    for (int im = 0; im < 8; im++) {
        float a0, a1;
        unpack2(acc[im], a0, a1);
        sred[q * 512 + im * 64 + o2]     = a0;
        sred[q * 512 + im * 64 + o2 + 1] = a1;
    }
    __syncthreads();
    for (int idx = tid; idx < 512; idx += 256) {
        int im = idx >> 6, o = idx & 63;
        float s = 0.f;
        #pragma unroll
        for (int qq = 0; qq < 8; qq++) s += sred[qq * 512 + idx];
        g_feat[(img0 + im) * 64 + o] = fmaxf(s + fcb[o], 0.f);
    }
}

// =========================================================================
// Kernel 4: Eq3to3 + relu + mean(ijk). j<->k symmetry: compute only
// upper-triangle 8x8 tile-blocks (10 of 16); epilogue emits both orderings.
// =========================================================================
#define EQ_SMEM ((2304 + 64 + 3*4352 + 2*2048 + 64 + 2048) * 4)
__global__ __launch_bounds__(256, 2) void eq_kernel(
    const float* __restrict__ eqw, const float* __restrict__ eqb)
{
    extern __shared__ float sm[];
    float* sat  = sm;            // [d][k] pad 36 : 2304
    float* sAb  = sat + 2304;    // 64
    float* sV   = sAb + 64;      // [d][e] pad 68 : 4352
    float* sCk  = sV  + 4352;
    float* sCj  = sCk + 4352;
    float* sgk  = sCj + 4352;    // [k][e] : 2048
    float* sgj  = sgk + 2048;    // [j][e] : 2048
    float* ssb  = sgj + 2048;    // 64
    float* sred = ssb + 64;      // 2048

    const int b   = blockIdx.x >> 5;
    const int ii  = blockIdx.x & 31;
    const int tid = threadIdx.x;

    const float* fb = g_feat + b * KK * HID;
    for (int idx = tid; idx < 2048; idx += 256) {
        int k = idx >> 6, d = idx & 63;
        sat[d * 36 + k] = fb[idx];
    }
    __syncthreads();
    if (tid < 64) {
        const float* row = sat + tid * 36;
        float s = 0.f;
        #pragma unroll
        for (int k = 0; k < 32; k++) s += row[k];
        sAb[tid] = s * (1.0f / 32.0f);
    }
    __syncthreads();

    for (int idx = tid; idx < 4096; idx += 256) {
        int d = idx >> 6, e = idx & 63;
        const float4* wp = (const float4*)(eqw + (size_t)idx * 8);
        float4 wA = wp[0];
        float4 wB = wp[1];
        float ai = sat[d * 36 + ii], ab = sAb[d];
        sV [d * 68 + e] = wA.x * ai + wA.y * ab;
        sCk[d * 68 + e] = ab * (wA.z * ai + wB.x * ab);
        sCj[d * 68 + e] = ab * (wA.w * ai + wB.y * ab);
    }
    if (tid < 64) {
        int e = tid;
        float s = 0.f;
        for (int d = 0; d < 64; d++) {
            float ab = sAb[d];
            float2 w67 = *(const float2*)(eqw + ((size_t)(d * 64 + e)) * 8 + 6);
            s += ab * ab * (w67.x * sat[d * 36 + ii] + w67.y * ab);
        }
        ssb[e] = s + eqb[e];
    }
    __syncthreads();

    for (int idx = tid; idx < 2048; idx += 256) {
        int k = idx >> 6, e = idx & 63;
        float s1 = 0.f, s2 = 0.f;
        #pragma unroll 8
        for (int d = 0; d < 64; d++) {
            float ak = sat[d * 36 + k];
            s1 += sCk[d * 68 + e] * ak;
            s2 += sCj[d * 68 + e] * ak;
        }
        sgk[k * 64 + e] = s1;
        sgj[k * 64 + e] = s2;
    }
    __syncthreads();

    const int eg   = tid & 7;
    const int jkg  = tid >> 3;
    const int slot = jkg >> 3;      // 0..3 (warp-pair uniform)
    const int jrow = jkg & 7;       // 0..7

    // upper-triangle tile-block map, 4-bit packed
    const u64 JT = 0x3221110000ull;
    const u64 KT = 0x3323213210ull;

    float esum[8];
    #pragma unroll
    for (int v = 0; v < 8; v++) esum[v] = 0.f;

    for (int pass = 0; pass < 3; pass++) {
        const int tb = pass * 4 + slot;
        if (tb >= 10) continue;     // 2 idle slots in pass 2 (warp-uniform)
        const int jt = (int)((JT >> (4 * tb)) & 15);
        const int kt = (int)((KT >> (4 * tb)) & 15);
        const int j  = jt * 8 + jrow;
        const int k0 = kt * 8;
        const bool diag = (jt == kt);

        u64 acc2[8][4];
        #pragma unroll
        for (int u = 0; u < 8; u++)
            #pragma unroll
            for (int v = 0; v < 4; v++) acc2[u][v] = 0ull;

        // software-pipelined d-loop
        float       ajn = sat[j];
        float4      kan = *(const float4*)(sat + k0);
        float4      kbn = *(const float4*)(sat + k0 + 4);
        ulonglong2  V0n = *(const ulonglong2*)(sV + eg * 8);
        ulonglong2  V1n = *(const ulonglong2*)(sV + eg * 8 + 4);

        #pragma unroll 4
        for (int d = 0; d < 64; d++) {
            float      aj = ajn;
            float4     ka = kan, kb = kbn;
            ulonglong2 V0 = V0n, V1 = V1n;
            if (d < 63) {
                const float* rn = sat + (d + 1) * 36;
                ajn = rn[j];
                kan = *(const float4*)(rn + k0);
                kbn = *(const float4*)(rn + k0 + 4);
                V0n = *(const ulonglong2*)(sV + (d + 1) * 68 + eg * 8);
                V1n = *(const ulonglong2*)(sV + (d + 1) * 68 + eg * 8 + 4);
            }
            u64 Vv[4] = {V0.x, V0.y, V1.x, V1.y};
            float akf[8] = {ka.x, ka.y, ka.z, ka.w, kb.x, kb.y, kb.z, kb.w};
            #pragma unroll
            for (int u = 0; u < 8; u++) {
                float pr = aj * akf[u];
                u64 prd = pack2(pr, pr);
                acc2[u][0] = ffma2(prd, Vv[0], acc2[u][0]);
                acc2[u][1] = ffma2(prd, Vv[1], acc2[u][1]);
                acc2[u][2] = ffma2(prd, Vv[2], acc2[u][2]);
                acc2[u][3] = ffma2(prd, Vv[3], acc2[u][3]);
            }
        }

        // epilogue: both orderings (j,k) and (k,j)
        const float* sbp  = ssb + eg * 8;
        const float* gj_j = sgj + j * 64 + eg * 8;
        const float* gk_j = sgk + j * 64 + eg * 8;
        float4 gjj0 = *(const float4*)(gj_j), gjj1 = *(const float4*)(gj_j + 4);
        float4 gkj0 = *(const float4*)(gk_j), gkj1 = *(const float4*)(gk_j + 4);
        float gjjv[8] = {gjj0.x, gjj0.y, gjj0.z, gjj0.w, gjj1.x, gjj1.y, gjj1.z, gjj1.w};
        float gkjv[8] = {gkj0.x, gkj0.y, gkj0.z, gkj0.w, gkj1.x, gkj1.y, gkj1.z, gkj1.w};

        #pragma unroll
        for (int u = 0; u < 8; u++) {
            const int k = k0 + u;
            const float* gk_k = sgk + k * 64 + eg * 8;
            const float* gj_k = sgj + k * 64 + eg * 8;
            float4 gkk0 = *(const float4*)(gk_k), gkk1 = *(const float4*)(gk_k + 4);
            float4 gjk0 = *(const float4*)(gj_k), gjk1 = *(const float4*)(gj_k + 4);
            float gkkv[8] = {gkk0.x, gkk0.y, gkk0.z, gkk0.w, gkk1.x, gkk1.y, gkk1.z, gkk1.w};
            float gjkv[8] = {gjk0.x, gjk0.y, gjk0.z, gjk0.w, gjk1.x, gjk1.y, gjk1.z, gjk1.w};

            const bool take1 = diag ? (k >= j) : true;
            const bool take2 = diag ? (k > j)  : true;

            #pragma unroll
            for (int v2 = 0; v2 < 4; v2++) {
                float a0, a1;
                unpack2(acc2[u][v2], a0, a1);
                float p0 = a0 + gjjv[2 * v2]     + gkkv[2 * v2]     + sbp[2 * v2];
                float p1 = a1 + gjjv[2 * v2 + 1] + gkkv[2 * v2 + 1] + sbp[2 * v2 + 1];
                float q0 = a0 + gjkv[2 * v2]     + gkjv[2 * v2]     + sbp[2 * v2];
                float q1 = a1 + gjkv[2 * v2 + 1] + gkjv[2 * v2 + 1] + sbp[2 * v2 + 1];
                if (take1) {
                    esum[2 * v2]     += fmaxf(p0, 0.f);
                    esum[2 * v2 + 1] += fmaxf(p1, 0.f);
                }
                if (take2) {
                    esum[2 * v2]     += fmaxf(q0, 0.f);
                    esum[2 * v2 + 1] += fmaxf(q1, 0.f);
                }
            }
        }
    }

    #pragma unroll
    for (int v = 0; v < 8; v++) sred[jkg * 64 + eg * 8 + v] = esum[v];
    __syncthreads();
    if (tid < 64) {
        float s = 0.f;
        #pragma unroll
        for (int g = 0; g < 32; g++) s += sred[g * 64 + tid];
        g_part[blockIdx.x * 64 + tid] = s;
    }
}

// =========================================================================
// Kernel 5: final
// =========================================================================
__global__ __launch_bounds__(64) void final_kernel(
    const float* __restrict__ outw, const float* __restrict__ outb,
    float* __restrict__ out)
{
    __shared__ float red[64];
    const int b = blockIdx.x, e = threadIdx.x;
    float s = 0.f;
    #pragma unroll
    for (int i = 0; i < 32; i++) s += g_part[(b * 32 + i) * 64 + e];
    float x8 = s * (1.0f / 32768.0f);
    red[e] = fmaxf(x8, 0.f) * outw[e];
    __syncthreads();
    #pragma unroll
    for (int off = 32; off; off >>= 1) {
        if (e < off) red[e] += red[e + off];
        __syncthreads();
    }
    if (e == 0) out[b] = red[0] + outb[0];
}

// =========================================================================
extern "C" void kernel_launch(void* const* d_in, const int* in_sizes, int n_in,
                              void* d_out, int out_size)
{
    const float* x    = (const float*)d_in[0];
    const float* c1w  = (const float*)d_in[1];
    const float* c1b  = (const float*)d_in[2];
    const float* c2w  = (const float*)d_in[3];
    const float* c2b  = (const float*)d_in[4];
    const float* fcw  = (const float*)d_in[5];
    const float* fcb  = (const float*)d_in[6];
    const float* eqw  = (const float*)d_in[7];
    const float* eqb  = (const float*)d_in[8];
    const float* outw = (const float*)d_in[9];
    const float* outb = (const float*)d_in[10];
    float* out = (float*)d_out;

    cudaFuncSetAttribute(conv2_kernel, cudaFuncAttributeMaxDynamicSharedMemorySize, CONV2_SMEM);
    cudaFuncSetAttribute(fc_kernel,    cudaFuncAttributeMaxDynamicSharedMemorySize, FC_SMEM);
    cudaFuncSetAttribute(eq_kernel,    cudaFuncAttributeMaxDynamicSharedMemorySize, EQ_SMEM);

    conv1_kernel<<<NIMG, 256>>>(x, c1w, c1b);
    conv2_kernel<<<NIMG, 256, CONV2_SMEM>>>(c2w, c2b);
    fc_kernel<<<64, 256, FC_SMEM>>>(fcw, fcb);
    eq_kernel<<<NIMG, 256, EQ_SMEM>>>(eqw, eqb);
    final_kernel<<<BB, 64>>>(outw, outb, out);
}

// round 7
// speedup vs baseline: 1.9765x; 1.0233x over previous
#include <cuda_runtime.h>
#include <cuda_bf16.h>
#include <math.h>

#define BB   16
#define KK   32
#define HH   28
#define WW   28
#define HID  64
#define OUT  64
#define NIMG (BB*KK)          // 512

typedef unsigned long long u64;

// ---------------- scratch ----------------
__device__ float g_h1[NIMG * 32 * 14 * 14];
__device__ float g_h2[NIMG * 64 * 7 * 7];
__device__ float g_feat[NIMG * HID];
__device__ float g_part[NIMG * OUT];

// ---------------- packed fp32x2 helpers ----------------
__device__ __forceinline__ u64 pack2(float x, float y) {
    u64 r; asm("mov.b64 %0,{%1,%2};" : "=l"(r) : "f"(x), "f"(y)); return r;
}
__device__ __forceinline__ void unpack2(u64 p, float& x, float& y) {
    asm("mov.b64 {%0,%1},%2;" : "=f"(x), "=f"(y) : "l"(p));
}
__device__ __forceinline__ u64 ffma2(u64 a, u64 b, u64 c) {
    u64 d; asm("fma.rn.f32x2 %0,%1,%2,%3;" : "=l"(d) : "l"(a), "l"(b), "l"(c)); return d;
}

// =========================================================================
// Kernel 1: conv1 (1->32, 3x3 SAME) + relu + maxpool2
// =========================================================================
__global__ __launch_bounds__(256) void conv1_kernel(
    const float* __restrict__ x, const float* __restrict__ w,
    const float* __restrict__ bias)
{
    __shared__ float sin1[30 * 30];
    __shared__ float sw1[32 * 9];
    __shared__ float sb1[32];

    const int img = blockIdx.x;
    const int tid = threadIdx.x;

    for (int i = tid; i < 900; i += 256) sin1[i] = 0.f;
    for (int i = tid; i < 288; i += 256) sw1[i] = w[i];
    if (tid < 32) sb1[tid] = bias[tid];
    __syncthreads();
    for (int i = tid; i < 784; i += 256) {
        int y = i / 28, xx = i % 28;
        sin1[(y + 1) * 30 + xx + 1] = x[img * 784 + i];
    }
    __syncthreads();

    for (int item = tid; item < 32 * 196; item += 256) {
        int c = item / 196, p = item % 196;
        int oy = p / 14, ox = p % 14;
        const float* wp = sw1 + c * 9;
        const float bv = sb1[c];
        float m = 0.f;
        #pragma unroll
        for (int py = 0; py < 2; py++) {
            #pragma unroll
            for (int px = 0; px < 2; px++) {
                int r = 2 * oy + py, col = 2 * ox + px;
                float s = bv;
                #pragma unroll
                for (int ky = 0; ky < 3; ky++)
                    #pragma unroll
                    for (int kx = 0; kx < 3; kx++)
                        s += sin1[(r + ky) * 30 + col + kx] * wp[ky * 3 + kx];
                m = fmaxf(m, s);
            }
        }
        g_h1[img * (32 * 196) + item] = m;
    }
}

// =========================================================================
// Kernel 2: conv2 (32->64) + relu + maxpool2, channel-lane mapping.
// warp = pooled position (warp-uniform), lane = ch-pair (64ch = 32 lanes x2).
// Input patch loads: warp-uniform broadcasts (conflict-free).
// Weight loads: lane-consecutive LDS.64 (conflict-free).
// =========================================================================
#define CONV2_SMEM ((8192 + 18432 + 64) * 4)
__global__ __launch_bounds__(256, 2) void conv2_kernel(
    const float* __restrict__ w, const float* __restrict__ bias)
{
    extern __shared__ float sm2[];
    float* sin2 = sm2;                 // [ic][16*16], zero-padded border
    float* sw2  = sm2 + 8192;          // [ic*9+r][64ch]
    float* sb2  = sw2 + 18432;

    const int img = blockIdx.x;
    const int tid = threadIdx.x;

    for (int i = tid; i < 8192; i += 256) sin2[i] = 0.f;
    for (int idx = tid; idx < 18432; idx += 256) {
        int f = idx >> 6, c = idx & 63;
        int ic = f / 9, r = f % 9;
        sw2[idx] = w[(c * 32 + ic) * 9 + r];
    }
    if (tid < 64) sb2[tid] = bias[tid];
    __syncthreads();
    for (int i = tid; i < 32 * 196; i += 256) {
        int ic = i / 196, p = i % 196;
        int y = p / 14, xx = p % 14;
        sin2[ic * 256 + (y + 1) * 16 + xx + 1] = g_h1[img * (32 * 196) + i];
    }
    __syncthreads();

    const int wid  = tid >> 5;
    const int lane = tid & 31;
    const int c0   = lane * 2;
    const float b0 = sb2[c0], b1 = sb2[c0 + 1];

    for (int s = 0; s < 7; s++) {
        const int pos = wid + 8 * s;     // warp-uniform
        if (pos >= 49) break;            // only warp 0 runs s=6 (pos 48)
        const int oy = pos / 7, ox = pos % 7;
        const int iy = 2 * oy, ix = 2 * ox;

        u64 acc[4];                      // 2x2 pool windows, ch-pair packed
        #pragma unroll
        for (int p = 0; p < 4; p++) acc[p] = 0ull;

        for (int ic = 0; ic < 32; ic++) {
            const float* ip = sin2 + ic * 256 + iy * 16 + ix;
            float pa[4][4];              // warp-uniform broadcast loads
            #pragma unroll
            for (int r = 0; r < 4; r++)
                #pragma unroll
                for (int cc = 0; cc < 4; cc++)
                    pa[r][cc] = ip[r * 16 + cc];

            const float* wic = sw2 + ic * 9 * 64 + c0;
            #pragma unroll
            for (int ky = 0; ky < 3; ky++) {
                #pragma unroll
                for (int kx = 0; kx < 3; kx++) {
                    u64 wv = *(const u64*)(wic + (ky * 3 + kx) * 64);
                    acc[0] = ffma2(pack2(pa[ky][kx],         pa[ky][kx]),         wv, acc[0]);
                    acc[1] = ffma2(pack2(pa[ky][kx + 1],     pa[ky][kx + 1]),     wv, acc[1]);
                    acc[2] = ffma2(pack2(pa[ky + 1][kx],     pa[ky + 1][kx]),     wv, acc[2]);
                    acc[3] = ffma2(pack2(pa[ky + 1][kx + 1], pa[ky + 1][kx + 1]), wv, acc[3]);
                }
            }
        }
        float a0[4], a1[4];
        #pragma unroll
        for (int p = 0; p < 4; p++) unpack2(acc[p], a0[p], a1[p]);
        float m0 = fmaxf(fmaxf(a0[0], a0[1]), fmaxf(a0[2], a0[3])) + b0;
        float m1 = fmaxf(fmaxf(a1[0], a1[1]), fmaxf(a1[2], a1[3])) + b1;
        g_h2[img * 3136 + c0 * 49 + pos]       = fmaxf(m0, 0.f);
        g_h2[img * 3136 + (c0 + 1) * 49 + pos] = fmaxf(m1, 0.f);
    }
}

// =========================================================================
// Kernel 3: fc, weight-stationary. 64 blocks x 8 images.
// =========================================================================
#define FC_CHUNK 392
#define FC_WPAD  66
#define FC_SMEM  ((8 * 3136 + FC_CHUNK * FC_WPAD) * 4)
__global__ __launch_bounds__(256) void fc_kernel(
    const float* __restrict__ fcw, const float* __restrict__ fcb)
{
    extern __shared__ float smf[];
    float* sact = smf;                  // [8][3136]
    float* swc  = smf + 8 * 3136;       // [392][66] transposed chunk

    const int tid  = threadIdx.x;
    const int img0 = blockIdx.x * 8;

    for (int idx = tid; idx < 8 * 3136; idx += 256)
        sact[idx] = g_h2[img0 * 3136 + idx];

    const int o2 = (tid & 31) * 2;
    const int q  = tid >> 5;

    u64 acc[8];
    #pragma unroll
    for (int im = 0; im < 8; im++) acc[im] = 0ull;

    for (int ch = 0; ch < 8; ch++) {
        __syncthreads();
        for (int idx = tid; idx < 64 * FC_CHUNK; idx += 256) {
            int o = idx / FC_CHUNK, i = idx % FC_CHUNK;
            swc[i * FC_WPAD + o] = fcw[(size_t)o * 3136 + ch * FC_CHUNK + i];
        }
        __syncthreads();

        const int ibase = q * 49;
        #pragma unroll 7
        for (int t = 0; t < 49; t++) {
            int i = ibase + t;
            u64 wv = *(const u64*)(swc + i * FC_WPAD + o2);
            int gi = ch * FC_CHUNK + i;
            #pragma unroll
            for (int im = 0; im < 8; im++) {
                float a = sact[im * 3136 + gi];
                acc[im] = ffma2(pack2(a, a), wv, acc[im]);
            }
        }
    }
    __syncthreads();

    float* sred = swc;
    #pragma unroll
    for (int im = 0; im < 8; im++) {
        float a0, a1;
        unpack2(acc[im], a0, a1);
        sred[q * 512 + im * 64 + o2]     = a0;
        sred[q * 512 + im * 64 + o2 + 1] = a1;
    }
    __syncthreads();
    for (int idx = tid; idx < 512; idx += 256) {
        int im = idx >> 6, o = idx & 63;
        float s = 0.f;
        #pragma unroll
        for (int qq = 0; qq < 8; qq++) s += sred[qq * 512 + idx];
        g_feat[(img0 + im) * 64 + o] = fmaxf(s + fcb[o], 0.f);
    }
}

// =========================================================================
// Kernel 4: Eq3to3 + relu + mean(ijk). Warp-tile rank-1 outer product:
// 320 threads = 10 warps = 10 upper-triangle 8x8 jk-tiles (warp-uniform
// j0/k0 -> aj/ak loads are broadcasts). lane = e (2 passes for 64 e);
// V/gj/gk/ssb loads are lane-consecutive (conflict-free). FMA-bound.
// =========================================================================
#define EQ_NT 320
#define EQ_SMEM ((2304 + 64 + 3*4352 + 2*2048 + 64 + 640) * 4)
__global__ __launch_bounds__(EQ_NT, 2) void eq_kernel(
    const float* __restrict__ eqw, const float* __restrict__ eqb)
{
    extern __shared__ float sm[];
    float* sat  = sm;            // [d][k] pad 36 : 2304
    float* sAb  = sat + 2304;    // 64
    float* sV   = sAb + 64;      // [d][e] pad 68 : 4352
    float* sCk  = sV  + 4352;
    float* sCj  = sCk + 4352;
    float* sgk  = sCj + 4352;    // [k][e] : 2048
    float* sgj  = sgk + 2048;    // [j][e] : 2048
    float* ssb  = sgj + 2048;    // 64
    float* sred = ssb + 64;      // [10 warps][64]

    const int b   = blockIdx.x >> 5;
    const int ii  = blockIdx.x & 31;
    const int tid = threadIdx.x;

    const float* fb = g_feat + b * KK * HID;
    for (int idx = tid; idx < 2048; idx += EQ_NT) {
        int k = idx >> 6, d = idx & 63;
        sat[d * 36 + k] = fb[idx];
    }
    __syncthreads();
    if (tid < 64) {
        const float* row = sat + tid * 36;
        float s = 0.f;
        #pragma unroll
        for (int k = 0; k < 32; k++) s += row[k];
        sAb[tid] = s * (1.0f / 32.0f);
    }
    __syncthreads();

    for (int idx = tid; idx < 4096; idx += EQ_NT) {
        int d = idx >> 6, e = idx & 63;
        const float4* wp = (const float4*)(eqw + (size_t)idx * 8);
        float4 wA = wp[0];   // w0 w1 w2 w3
        float4 wB = wp[1];   // w4 w5 w6 w7
        float ai = sat[d * 36 + ii], ab = sAb[d];
        sV [d * 68 + e] = wA.x * ai + wA.y * ab;
        sCk[d * 68 + e] = ab * (wA.z * ai + wB.x * ab);
        sCj[d * 68 + e] = ab * (wA.w * ai + wB.y * ab);
    }
    if (tid < 64) {
        int e = tid;
        float s = 0.f;
        for (int d = 0; d < 64; d++) {
            float ab = sAb[d];
            float2 w67 = *(const float2*)(eqw + ((size_t)(d * 64 + e)) * 8 + 6);
            s += ab * ab * (w67.x * sat[d * 36 + ii] + w67.y * ab);
        }
        ssb[e] = s + eqb[e];
    }
    __syncthreads();

    for (int idx = tid; idx < 2048; idx += EQ_NT) {
        int k = idx >> 6, e = idx & 63;
        float s1 = 0.f, s2 = 0.f;
        #pragma unroll 8
        for (int d = 0; d < 64; d++) {
            float ak = sat[d * 36 + k];
            s1 += sCk[d * 68 + e] * ak;
            s2 += sCj[d * 68 + e] * ak;
        }
        sgk[k * 64 + e] = s1;
        sgj[k * 64 + e] = s2;
    }
    __syncthreads();

    // ---------------- warp-tile main loop ----------------
    const int w    = tid >> 5;      // warp = tile 0..9
    const int lane = tid & 31;

    const u64 JT = 0x3221110000ull;
    const u64 KT = 0x3323213210ull;
    const int jt = (int)((JT >> (4 * w)) & 15);
    const int kt = (int)((KT >> (4 * w)) & 15);
    const int j0 = jt * 8;
    const int k0 = kt * 8;
    const bool diag = (jt == kt);

    float esum0 = 0.f, esum1 = 0.f;

    #pragma unroll
    for (int pass = 0; pass < 2; pass++) {
        const int e = lane + 32 * pass;

        u64 acc[8][4];
        #pragma unroll
        for (int jj = 0; jj < 8; jj++)
            #pragma unroll
            for (int kp = 0; kp < 4; kp++) acc[jj][kp] = 0ull;

        for (int d = 0; d < 64; d++) {
            const float* rd = sat + d * 36;
            float vl = sV[d * 68 + e];               // lane-consecutive
            float aj[8];
            #pragma unroll
            for (int jj = 0; jj < 8; jj++) aj[jj] = rd[j0 + jj];   // broadcast
            u64 ak[4];
            #pragma unroll
            for (int kp = 0; kp < 4; kp++)
                ak[kp] = *(const u64*)(rd + k0 + 2 * kp);          // broadcast

            #pragma unroll
            for (int jj = 0; jj < 8; jj++) {
                float tv = aj[jj] * vl;
                u64 tp = pack2(tv, tv);
                acc[jj][0] = ffma2(tp, ak[0], acc[jj][0]);
                acc[jj][1] = ffma2(tp, ak[1], acc[jj][1]);
                acc[jj][2] = ffma2(tp, ak[2], acc[jj][2]);
                acc[jj][3] = ffma2(tp, ak[3], acc[jj][3]);
            }
        }

        // epilogue: both orderings (j,k) and (k,j)
        const float sbv = ssb[e];
        float es = 0.f;
        #pragma unroll
        for (int jj = 0; jj < 8; jj++) {
            const int j = j0 + jj;
            const float gjj = sgj[j * 64 + e];
            const float gkj = sgk[j * 64 + e];
            #pragma unroll
            for (int kp = 0; kp < 4; kp++) {
                float a0, a1;
                unpack2(acc[jj][kp], a0, a1);
                const int ka = k0 + 2 * kp;
                const int kb = ka + 1;
                float gkka = sgk[ka * 64 + e], gjka = sgj[ka * 64 + e];
                float gkkb = sgk[kb * 64 + e], gjkb = sgj[kb * 64 + e];
                float p0 = a0 + gjj + gkka + sbv;    // (j, ka)
                float q0 = a0 + gjka + gkj + sbv;    // (ka, j)
                float p1 = a1 + gjj + gkkb + sbv;    // (j, kb)
                float q1 = a1 + gjkb + gkj + sbv;    // (kb, j)
                if (!diag || ka >= j) es += fmaxf(p0, 0.f);
                if (!diag || ka >  j) es += fmaxf(q0, 0.f);
                if (!diag || kb >= j) es += fmaxf(p1, 0.f);
                if (!diag || kb >  j) es += fmaxf(q1, 0.f);
            }
        }
        if (pass == 0) esum0 = es; else esum1 = es;
    }

    sred[w * 64 + lane]      = esum0;
    sred[w * 64 + lane + 32] = esum1;
    __syncthreads();
    if (tid < 64) {
        float s = 0.f;
        #pragma unroll
        for (int g = 0; g < 10; g++) s += sred[g * 64 + tid];
        g_part[blockIdx.x * 64 + tid] = s;
    }
}

// =========================================================================
// Kernel 5: final
// =========================================================================
__global__ __launch_bounds__(64) void final_kernel(
    const float* __restrict__ outw, const float* __restrict__ outb,
    float* __restrict__ out)
{
    __shared__ float red[64];
    const int b = blockIdx.x, e = threadIdx.x;
    float s = 0.f;
    #pragma unroll
    for (int i = 0; i < 32; i++) s += g_part[(b * 32 + i) * 64 + e];
    float x8 = s * (1.0f / 32768.0f);
    red[e] = fmaxf(x8, 0.f) * outw[e];
    __syncthreads();
    #pragma unroll
    for (int off = 32; off; off >>= 1) {
        if (e < off) red[e] += red[e + off];
        __syncthreads();
    }
    if (e == 0) out[b] = red[0] + outb[0];
}

// =========================================================================
extern "C" void kernel_launch(void* const* d_in, const int* in_sizes, int n_in,
                              void* d_out, int out_size)
{
    const float* x    = (const float*)d_in[0];
    const float* c1w  = (const float*)d_in[1];
    const float* c1b  = (const float*)d_in[2];
    const float* c2w  = (const float*)d_in[3];
    const float* c2b  = (const float*)d_in[4];
    const float* fcw  = (const float*)d_in[5];
    const float* fcb  = (const float*)d_in[6];
    const float* eqw  = (const float*)d_in[7];
    const float* eqb  = (const float*)d_in[8];
    const float* outw = (const float*)d_in[9];
    const float* outb = (const float*)d_in[10];
    float* out = (float*)d_out;

    cudaFuncSetAttribute(conv2_kernel, cudaFuncAttributeMaxDynamicSharedMemorySize, CONV2_SMEM);
    cudaFuncSetAttribute(fc_kernel,    cudaFuncAttributeMaxDynamicSharedMemorySize, FC_SMEM);
    cudaFuncSetAttribute(eq_kernel,    cudaFuncAttributeMaxDynamicSharedMemorySize, EQ_SMEM);

    conv1_kernel<<<NIMG, 256>>>(x, c1w, c1b);
    conv2_kernel<<<NIMG, 256, CONV2_SMEM>>>(c2w, c2b);
    fc_kernel<<<64, 256, FC_SMEM>>>(fcw, fcb);
    eq_kernel<<<NIMG, EQ_NT, EQ_SMEM>>>(eqw, eqb);
    final_kernel<<<BB, 64>>>(outw, outb, out);
}